// round 9
// baseline (speedup 1.0000x reference)
#include <cuda_runtime.h>
#include <cuda_bf16.h>

// ---------------------------------------------------------------------------
// QueryInitialization: pos-resize + det/cls heads + top-k + query MLPs
// B=16, C=256, H=W=100 (N=10000), pos 50x50, det_k=100, rec_k=25
// Outputs concatenated: det[16,100,256] | rec[16,25,256] |
//                       cls[16,10000,2] | bbox[16,10000,4]
// ---------------------------------------------------------------------------

#define BATCH 16
#define CH    256
#define NPOS  10000
#define HPIX  100
#define PHW   50
#define KDET  100
#define KREC  25

#define DET_OFF  0
#define REC_OFF  (BATCH*KDET*CH)                 // 409600
#define CLS_OFF  (REC_OFF + BATCH*KREC*CH)       // 512000
#define BBX_OFF  (CLS_OFF + BATCH*NPOS*2)        // 832000

// scratch (__device__ globals, accessed ONLY from device code — never passed
// as host-side kernel arguments, which would hand the kernel the host shadow
// address and grow UVM pools via ATS on the Grace host).
__device__ float  g_posdot[NPOS * 6];      // pos @ [Wc;Wb]^T + bias, per n
__device__ int    g_idx[BATCH * KDET];     // sorted top-100 indices per batch
__device__ float2 g_WT2[6 * (CH / 2) * CH];// transposed+paired MLP weights

// ---------------------------------------------------------------------------
// f32x2 packed helpers (Blackwell FFMA2)
// ---------------------------------------------------------------------------
__device__ __forceinline__ unsigned long long pack2(float x, float y) {
    unsigned long long r;
    asm("mov.b64 %0, {%1,%2};" : "=l"(r) : "f"(x), "f"(y));
    return r;
}
__device__ __forceinline__ float2 unpack2(unsigned long long v) {
    float2 f;
    asm("mov.b64 {%0,%1}, %2;" : "=f"(f.x), "=f"(f.y) : "l"(v));
    return f;
}
__device__ __forceinline__ unsigned long long ffma2(
    unsigned long long a, unsigned long long b, unsigned long long c) {
    unsigned long long d;
    asm("fma.rn.f32x2 %0, %1, %2, %3;" : "=l"(d) : "l"(a), "l"(b), "l"(c));
    return d;
}

// ---------------------------------------------------------------------------
// bilinear coefficients for output pixel (y,x) of the 50->100 upsample
// (align_corners=False; matches torch/jax reference)
// ---------------------------------------------------------------------------
__device__ __forceinline__ void bilin_coef(int y, int x,
                                           int& i00, int& i01, int& i10, int& i11,
                                           float& w00, float& w01,
                                           float& w10, float& w11) {
    float sy = 0.5f * (float)y - 0.25f;
    sy = fminf(fmaxf(sy, 0.0f), (float)(PHW - 1));
    int   y0 = (int)floorf(sy);
    float ty = sy - (float)y0;
    int   y1 = min(y0 + 1, PHW - 1);

    float sx = 0.5f * (float)x - 0.25f;
    sx = fminf(fmaxf(sx, 0.0f), (float)(PHW - 1));
    int   x0 = (int)floorf(sx);
    float tx = sx - (float)x0;
    int   x1 = min(x0 + 1, PHW - 1);

    i00 = y0 * PHW + x0;  i01 = y0 * PHW + x1;
    i10 = y1 * PHW + x0;  i11 = y1 * PHW + x1;
    w00 = (1.0f - ty) * (1.0f - tx);
    w01 = (1.0f - ty) * tx;
    w10 = ty * (1.0f - tx);
    w11 = ty * tx;
}

// ---------------------------------------------------------------------------
// Kernel 0c: transpose MLP weights into pair-packed layout:
// g_WT2[l][(c>>1)*256 + o] = {W[o*256+c], W[o*256+c+1]}
// ---------------------------------------------------------------------------
__global__ void __launch_bounds__(256) k_wtrans(
        const float* __restrict__ dW1, const float* __restrict__ dW2,
        const float* __restrict__ dW3, const float* __restrict__ rW1,
        const float* __restrict__ rW2, const float* __restrict__ rW3) {
    __shared__ float tile[32][33];
    int l = blockIdx.z;
    const float* W;
    switch (l) {
        case 0: W = dW1; break;
        case 1: W = dW2; break;
        case 2: W = dW3; break;
        case 3: W = rW1; break;
        case 4: W = rW2; break;
        default: W = rW3; break;
    }
    int oo = blockIdx.x * 32;    // output-row tile base
    int co = blockIdx.y * 32;    // input-col tile base
    int tx = threadIdx.x, ty = threadIdx.y;

#pragma unroll
    for (int k = 0; k < 4; k++) {
        int row = ty + 8 * k;    // o_local
        tile[row][tx] = W[(oo + row) * CH + (co + tx)];
    }
    __syncthreads();

    float2* dst = g_WT2 + l * ((CH / 2) * CH);
#pragma unroll
    for (int k = 0; k < 2; k++) {
        int c2l = ty + 8 * k;    // pair index within tile (0..15)
        float2 v = make_float2(tile[tx][2 * c2l], tile[tx][2 * c2l + 1]);
        dst[(co / 2 + c2l) * CH + (oo + tx)] = v;
    }
}

// ---------------------------------------------------------------------------
// shared helper: pack the 6 head-weight rows channel-major in smem
// ---------------------------------------------------------------------------
__device__ __forceinline__ void load_wpack(float (*wpack)[8],
                                           const float* __restrict__ Wc,
                                           const float* __restrict__ Wb,
                                           int tid) {
    if (tid < CH) {
        wpack[tid][0] = Wc[tid];
        wpack[tid][1] = Wc[CH + tid];
        wpack[tid][2] = Wb[tid];
        wpack[tid][3] = Wb[CH + tid];
        wpack[tid][4] = Wb[2 * CH + tid];
        wpack[tid][5] = Wb[3 * CH + tid];
        wpack[tid][6] = 0.f;
        wpack[tid][7] = 0.f;
    }
}

// ---------------------------------------------------------------------------
// Kernel 0b: g_posdot[n][j] = bias_j + sum_c pos[c][n] * Wrow_j[c]
// pos computed inline from pe (bilinear); pe is 2.5 MB -> L2-resident.
// ---------------------------------------------------------------------------
__global__ void __launch_bounds__(256) k_posdot(
        const float* __restrict__ pe,
        const float* __restrict__ Wc, const float* __restrict__ bc,
        const float* __restrict__ Wb, const float* __restrict__ bb) {
    __shared__ float wpack[CH][8];
    int tid = threadIdx.x;
    load_wpack(wpack, Wc, Wb, tid);
    __syncthreads();

    int n = blockIdx.x * blockDim.x + tid;
    if (n >= NPOS) return;

    int i00, i01, i10, i11;
    float w00, w01, w10, w11;
    bilin_coef(n / HPIX, n % HPIX, i00, i01, i10, i11, w00, w01, w10, w11);

    float acc0 = bc[0], acc1 = bc[1];
    float acc2 = bb[0], acc3 = bb[1], acc4 = bb[2], acc5 = bb[3];

#pragma unroll 4
    for (int c = 0; c < CH; c++) {
        const float* P = pe + c * (PHW * PHW);
        float p = P[i00] * w00 + P[i01] * w01 + P[i10] * w10 + P[i11] * w11;
        float4 w0 = *(const float4*)&wpack[c][0];
        float4 w1 = *(const float4*)&wpack[c][4];
        acc0 += p * w0.x; acc1 += p * w0.y;
        acc2 += p * w0.z; acc3 += p * w0.w;
        acc4 += p * w1.x; acc5 += p * w1.y;
    }
    float* dst = g_posdot + n * 6;
    dst[0] = acc0; dst[1] = acc1; dst[2] = acc2;
    dst[3] = acc3; dst[4] = acc4; dst[5] = acc5;
}

// ---------------------------------------------------------------------------
// Kernel A: main pass. Reads x once (163 MB, HBM-bound); cls/bbox to out.
// ---------------------------------------------------------------------------
__global__ void __launch_bounds__(256) k_heads(
        const float* __restrict__ X, const float* __restrict__ Wc,
        const float* __restrict__ Wb, float* __restrict__ out) {
    __shared__ float wpack[CH][8];
    int tid = threadIdx.x;
    load_wpack(wpack, Wc, Wb, tid);
    __syncthreads();

    int b = blockIdx.y;
    int n = blockIdx.x * blockDim.x + tid;
    if (n >= NPOS) return;

    const float* pd = g_posdot + n * 6;
    float acc0 = pd[0], acc1 = pd[1], acc2 = pd[2];
    float acc3 = pd[3], acc4 = pd[4], acc5 = pd[5];

    const float* xp = X + (size_t)b * (CH * NPOS) + n;
#pragma unroll 8
    for (int c = 0; c < CH; c++) {
        float xv = xp[(size_t)c * NPOS];
        float4 w0 = *(const float4*)&wpack[c][0];
        float4 w1 = *(const float4*)&wpack[c][4];
        acc0 += xv * w0.x; acc1 += xv * w0.y;
        acc2 += xv * w0.z; acc3 += xv * w0.w;
        acc4 += xv * w1.x; acc5 += xv * w1.y;
    }

    int bn = b * NPOS + n;
    *(float2*)&out[CLS_OFF + (size_t)bn * 2] = make_float2(acc0, acc1);
    *(float4*)&out[BBX_OFF + (size_t)bn * 4] = make_float4(acc2, acc3, acc4, acc5);
}

// ---------------------------------------------------------------------------
// Kernel B: exact top-100 per batch (sorted desc, ties -> lower index first,
// matching jax.lax.top_k). One block of 512 threads per batch.
// Scores recomputed from cls logits in d_out (harness pointer argument):
// score = l1 - l0, monotonic with softmax conf[...,1].
// 20 named scalar u64 keys; 128-reg budget at 512 thr -> no spill.
// ---------------------------------------------------------------------------
__device__ __forceinline__ unsigned int ord_float(float f) {
    unsigned int b = __float_as_uint(f);
    return (b & 0x80000000u) ? ~b : (b | 0x80000000u);
}
__device__ __forceinline__ unsigned long long u64max(unsigned long long a,
                                                     unsigned long long b) {
    return a > b ? a : b;
}
__device__ __forceinline__ unsigned long long warp_max_u64(unsigned long long v) {
#pragma unroll
    for (int off = 16; off > 0; off >>= 1) {
        unsigned long long o = __shfl_down_sync(0xffffffffu, v, off);
        v = (o > v) ? o : v;
    }
    return v;
}

__global__ void __launch_bounds__(512, 1) k_topk(const float* __restrict__ cls) {
    __shared__ unsigned long long warpmax[16];
    __shared__ unsigned long long win_s;

    int b   = blockIdx.x;
    int tid = threadIdx.x;
    int lane = tid & 31, wid = tid >> 5;

    const float2* sp = (const float2*)(cls + (size_t)b * NPOS * 2);

#define MKKEY(J)                                                               \
    unsigned long long k##J = 0;                                               \
    {                                                                          \
        int n = tid + (J) * 512;                                               \
        if (n < NPOS) {                                                        \
            float2 l = sp[n];                                                  \
            k##J = ((unsigned long long)ord_float(l.y - l.x) << 32) |          \
                   (unsigned long long)(0xFFFFFFFFu - (unsigned int)n);        \
        }                                                                      \
    }
    MKKEY(0)  MKKEY(1)  MKKEY(2)  MKKEY(3)  MKKEY(4)
    MKKEY(5)  MKKEY(6)  MKKEY(7)  MKKEY(8)  MKKEY(9)
    MKKEY(10) MKKEY(11) MKKEY(12) MKKEY(13) MKKEY(14)
    MKKEY(15) MKKEY(16) MKKEY(17) MKKEY(18) MKKEY(19)
#undef MKKEY

#pragma unroll 1
    for (int i = 0; i < KDET; i++) {
        unsigned long long m =
            u64max(u64max(u64max(u64max(k0, k1),  u64max(k2, k3)),
                          u64max(u64max(k4, k5),  u64max(k6, k7))),
                   u64max(u64max(u64max(k8, k9),  u64max(k10, k11)),
                          u64max(u64max(k12, k13),
                                 u64max(u64max(k14, k15),
                                        u64max(u64max(k16, k17),
                                               u64max(k18, k19))))));
        m = warp_max_u64(m);
        if (lane == 0) warpmax[wid] = m;
        __syncthreads();
        if (wid == 0) {
            unsigned long long v = (lane < 16) ? warpmax[lane] : 0ull;
            v = warp_max_u64(v);
            if (lane == 0) win_s = v;
        }
        __syncthreads();
        unsigned long long w = win_s;
        if (tid == 0)
            g_idx[b * KDET + i] =
                (int)(0xFFFFFFFFu - (unsigned int)(w & 0xFFFFFFFFull));
        // kill winner by value (keys unique: index embedded in low bits)
        k0  = (k0  == w) ? 0 : k0;   k1  = (k1  == w) ? 0 : k1;
        k2  = (k2  == w) ? 0 : k2;   k3  = (k3  == w) ? 0 : k3;
        k4  = (k4  == w) ? 0 : k4;   k5  = (k5  == w) ? 0 : k5;
        k6  = (k6  == w) ? 0 : k6;   k7  = (k7  == w) ? 0 : k7;
        k8  = (k8  == w) ? 0 : k8;   k9  = (k9  == w) ? 0 : k9;
        k10 = (k10 == w) ? 0 : k10;  k11 = (k11 == w) ? 0 : k11;
        k12 = (k12 == w) ? 0 : k12;  k13 = (k13 == w) ? 0 : k13;
        k14 = (k14 == w) ? 0 : k14;  k15 = (k15 == w) ? 0 : k15;
        k16 = (k16 == w) ? 0 : k16;  k17 = (k17 == w) ? 0 : k17;
        k18 = (k18 == w) ? 0 : k18;  k19 = (k19 == w) ? 0 : k19;
    }
}

// ---------------------------------------------------------------------------
// Kernel C: gather selected features (x + pos) and run 3-layer MLP + query.
// Blocks 0..99 = det (16 rows each), 100..124 = rec (16 rows each).
// 256 threads; thread tid owns output neuron o = tid for ALL 16 rows.
// buf layout: buf[c*20 + r], r = 0..15 (stride-20 padding, 16B-aligned).
// Per channel-pair: broadcast LDS.128 of all 16 rows x 2 channels,
// 16 FFMA2 into 8 u64 accumulators (16 row values).
// ---------------------------------------------------------------------------
#define BUF_STRIDE 20

__device__ __forceinline__ void mlp_layer(float* __restrict__ buf,
                                          const float2* __restrict__ WT,
                                          const float* __restrict__ bias,
                                          bool relu, int o) {
    float bv = bias[o];
    unsigned long long a0 = pack2(bv, bv);
    unsigned long long a1 = a0, a2 = a0, a3 = a0;
    unsigned long long a4 = a0, a5 = a0, a6 = a0, a7 = a0;

    const float2* wp = WT + o;
#pragma unroll 2
    for (int c2 = 0; c2 < CH / 2; c2++) {
        float2 w2 = wp[c2 * CH];
        unsigned long long w0 = pack2(w2.x, w2.x);
        unsigned long long w1 = pack2(w2.y, w2.y);
        const float* base0 = buf + (2 * c2) * BUF_STRIDE;
        const float* base1 = buf + (2 * c2 + 1) * BUF_STRIDE;
        {   // channel 2*c2, rows 0..15
            ulonglong2 u0 = *(const ulonglong2*)(base0 + 0);
            ulonglong2 u1 = *(const ulonglong2*)(base0 + 4);
            ulonglong2 u2 = *(const ulonglong2*)(base0 + 8);
            ulonglong2 u3 = *(const ulonglong2*)(base0 + 12);
            a0 = ffma2(u0.x, w0, a0);  a1 = ffma2(u0.y, w0, a1);
            a2 = ffma2(u1.x, w0, a2);  a3 = ffma2(u1.y, w0, a3);
            a4 = ffma2(u2.x, w0, a4);  a5 = ffma2(u2.y, w0, a5);
            a6 = ffma2(u3.x, w0, a6);  a7 = ffma2(u3.y, w0, a7);
        }
        {   // channel 2*c2+1, rows 0..15
            ulonglong2 u0 = *(const ulonglong2*)(base1 + 0);
            ulonglong2 u1 = *(const ulonglong2*)(base1 + 4);
            ulonglong2 u2 = *(const ulonglong2*)(base1 + 8);
            ulonglong2 u3 = *(const ulonglong2*)(base1 + 12);
            a0 = ffma2(u0.x, w1, a0);  a1 = ffma2(u0.y, w1, a1);
            a2 = ffma2(u1.x, w1, a2);  a3 = ffma2(u1.y, w1, a3);
            a4 = ffma2(u2.x, w1, a4);  a5 = ffma2(u2.y, w1, a5);
            a6 = ffma2(u3.x, w1, a6);  a7 = ffma2(u3.y, w1, a7);
        }
    }
    __syncthreads();   // everyone done reading buf
    {
        float2 r0 = unpack2(a0), r1 = unpack2(a1);
        float2 r2 = unpack2(a2), r3 = unpack2(a3);
        float2 r4 = unpack2(a4), r5 = unpack2(a5);
        float2 r6 = unpack2(a6), r7 = unpack2(a7);
        if (relu) {
            r0.x = fmaxf(r0.x, 0.f); r0.y = fmaxf(r0.y, 0.f);
            r1.x = fmaxf(r1.x, 0.f); r1.y = fmaxf(r1.y, 0.f);
            r2.x = fmaxf(r2.x, 0.f); r2.y = fmaxf(r2.y, 0.f);
            r3.x = fmaxf(r3.x, 0.f); r3.y = fmaxf(r3.y, 0.f);
            r4.x = fmaxf(r4.x, 0.f); r4.y = fmaxf(r4.y, 0.f);
            r5.x = fmaxf(r5.x, 0.f); r5.y = fmaxf(r5.y, 0.f);
            r6.x = fmaxf(r6.x, 0.f); r6.y = fmaxf(r6.y, 0.f);
            r7.x = fmaxf(r7.x, 0.f); r7.y = fmaxf(r7.y, 0.f);
        }
        float* dst = buf + o * BUF_STRIDE;
        *(float2*)(dst + 0)  = r0;  *(float2*)(dst + 2)  = r1;
        *(float2*)(dst + 4)  = r2;  *(float2*)(dst + 6)  = r3;
        *(float2*)(dst + 8)  = r4;  *(float2*)(dst + 10) = r5;
        *(float2*)(dst + 12) = r6;  *(float2*)(dst + 14) = r7;
    }
    __syncthreads();   // buf ready for next layer
}

__global__ void __launch_bounds__(256) k_mlp(
        const float* __restrict__ X, const float* __restrict__ pe,
        const float* __restrict__ db1, const float* __restrict__ db2,
        const float* __restrict__ db3,
        const float* __restrict__ rb1, const float* __restrict__ rb2,
        const float* __restrict__ rb3,
        const float* __restrict__ det_q, const float* __restrict__ rec_q,
        float* __restrict__ out) {
    __shared__ float buf[CH * BUF_STRIDE];   // 20 KB
    __shared__ int   s_n[16], s_b[16], s_q[16];
    __shared__ int   s_i00[16], s_i01[16], s_i10[16], s_i11[16];
    __shared__ float s_w00[16], s_w01[16], s_w10[16], s_w11[16];

    int tid = threadIdx.x;
    int blk = blockIdx.x;
    bool isdet = (blk < 100);
    int rowbase = isdet ? blk * 16 : (blk - 100) * 16;

    if (tid < 16) {
        int row = rowbase + tid;
        int b, q;
        if (isdet) { b = row / KDET; q = row % KDET; }
        else       { b = row / KREC; q = row % KREC; }
        s_b[tid] = b;
        s_q[tid] = q;
        int n = g_idx[b * KDET + q];
        s_n[tid] = n;
        int i00, i01, i10, i11;
        float w00, w01, w10, w11;
        bilin_coef(n / HPIX, n % HPIX, i00, i01, i10, i11, w00, w01, w10, w11);
        s_i00[tid] = i00; s_i01[tid] = i01; s_i10[tid] = i10; s_i11[tid] = i11;
        s_w00[tid] = w00; s_w01[tid] = w01; s_w10[tid] = w10; s_w11[tid] = w11;
    }
    __syncthreads();

    // gather: buf[c*20 + r] = x[b,c,n] + pos(c,n)   (pos inlined from pe)
    {
        int c = tid;
        const float* P = pe + c * (PHW * PHW);
#pragma unroll 4
        for (int r = 0; r < 16; r++) {
            float pv = P[s_i00[r]] * s_w00[r] + P[s_i01[r]] * s_w01[r] +
                       P[s_i10[r]] * s_w10[r] + P[s_i11[r]] * s_w11[r];
            buf[c * BUF_STRIDE + r] =
                X[((size_t)s_b[r] * CH + c) * NPOS + s_n[r]] + pv;
        }
    }
    __syncthreads();

    const float *B1, *B2, *B3, *Q;
    const float2* WT = g_WT2 + (isdet ? 0 : 3) * ((CH / 2) * CH);
    if (isdet) { B1 = db1; B2 = db2; B3 = db3; Q = det_q; }
    else       { B1 = rb1; B2 = rb2; B3 = rb3; Q = rec_q; }

    mlp_layer(buf, WT,                     B1, true,  tid);
    mlp_layer(buf, WT + (CH / 2) * CH,     B2, true,  tid);
    mlp_layer(buf, WT + 2 * (CH / 2) * CH, B3, false, tid);

    // epilogue: add query embedding, write output
    {
        int c = tid;
#pragma unroll 4
        for (int r = 0; r < 16; r++) {
            int row = rowbase + r;
            float v = buf[c * BUF_STRIDE + r] + Q[s_q[r] * CH + c];
            size_t dst = isdet ? (DET_OFF + (size_t)row * CH + c)
                               : (REC_OFF + (size_t)row * CH + c);
            out[dst] = v;
        }
    }
}

// ---------------------------------------------------------------------------
// launch  (no static initializers, no attribute calls, no allocation APIs,
// no __device__ symbols passed as kernel arguments, every kernel has args)
// ---------------------------------------------------------------------------
extern "C" void kernel_launch(void* const* d_in, const int* in_sizes, int n_in,
                              void* d_out, int out_size) {
    const float* X    = (const float*)d_in[0];
    const float* Wc   = (const float*)d_in[1];
    const float* bc   = (const float*)d_in[2];
    const float* Wb   = (const float*)d_in[3];
    const float* bb   = (const float*)d_in[4];
    const float* dW1  = (const float*)d_in[5];
    const float* db1  = (const float*)d_in[6];
    const float* dW2  = (const float*)d_in[7];
    const float* db2  = (const float*)d_in[8];
    const float* dW3  = (const float*)d_in[9];
    const float* db3  = (const float*)d_in[10];
    const float* rW1  = (const float*)d_in[11];
    const float* rb1  = (const float*)d_in[12];
    const float* rW2  = (const float*)d_in[13];
    const float* rb2  = (const float*)d_in[14];
    const float* rW3  = (const float*)d_in[15];
    const float* rb3  = (const float*)d_in[16];
    const float* detq = (const float*)d_in[17];
    const float* recq = (const float*)d_in[18];
    const float* pe   = (const float*)d_in[19];
    float* out = (float*)d_out;

    // 0b: pos-dot precompute (folds pos out of the hot pass; pos inlined)
    k_posdot<<<(NPOS + 255) / 256, 256>>>(pe, Wc, bc, Wb, bb);
    // 0c: pack/transpose MLP weights
    {
        dim3 grid(CH / 32, CH / 32, 6);
        dim3 blockd(32, 8);
        k_wtrans<<<grid, blockd>>>(dW1, dW2, dW3, rW1, rW2, rW3);
    }
    // A: heads (HBM-bound main pass; writes cls+bbox into out)
    {
        dim3 grid((NPOS + 255) / 256, BATCH);
        k_heads<<<grid, 256>>>(X, Wc, Wb, out);
    }
    // B: exact sorted top-100 per batch (scores recomputed from cls in out)
    k_topk<<<BATCH, 512>>>(out + CLS_OFF);
    // C: gather + MLPs + queries
    k_mlp<<<125, 256>>>(X, pe, db1, db2, db3, rb1, rb2, rb3, detq, recq, out);
}

// round 10
// speedup vs baseline: 1.2871x; 1.2871x over previous
#include <cuda_runtime.h>
#include <cuda_bf16.h>

// ---------------------------------------------------------------------------
// QueryInitialization: pos-resize + det/cls heads + top-k + query MLPs
// B=16, C=256, H=W=100 (N=10000), pos 50x50, det_k=100, rec_k=25
// Outputs concatenated: det[16,100,256] | rec[16,25,256] |
//                       cls[16,10000,2] | bbox[16,10000,4]
// ---------------------------------------------------------------------------

#define BATCH 16
#define CH    256
#define NPOS  10000
#define HPIX  100
#define PHW   50
#define KDET  100
#define KREC  25

#define DET_OFF  0
#define REC_OFF  (BATCH*KDET*CH)                 // 409600
#define CLS_OFF  (REC_OFF + BATCH*KREC*CH)       // 512000
#define BBX_OFF  (CLS_OFF + BATCH*NPOS*2)        // 832000

// top-k chunking: 5 chunks x 2000 elements (padded to 2048 for bitonic)
#define NCHUNK  5
#define CHUNKN  2000
#define CPAD    2048
#define MERGEN  (NCHUNK * KDET)   // 500 candidates
#define MPAD    512

// scratch (__device__ globals, accessed ONLY from device code — never passed
// as host-side kernel arguments: that hands the kernel the host shadow
// address, which ATS on the Grace host silently services -> UVM pool growth
// -> harness memory violation. Root cause of rounds 1-8.)
__device__ float  g_posdot[NPOS * 6];                 // pos@[Wc;Wb]^T + bias
__device__ int    g_idx[BATCH * KDET];                // sorted top-100 / batch
__device__ float2 g_WT2[6 * (CH / 2) * CH];           // packed MLP weights
__device__ unsigned long long g_cand[BATCH * MERGEN]; // chunk top-100 keys

// ---------------------------------------------------------------------------
// f32x2 packed helpers (Blackwell FFMA2)
// ---------------------------------------------------------------------------
__device__ __forceinline__ unsigned long long pack2(float x, float y) {
    unsigned long long r;
    asm("mov.b64 %0, {%1,%2};" : "=l"(r) : "f"(x), "f"(y));
    return r;
}
__device__ __forceinline__ float2 unpack2(unsigned long long v) {
    float2 f;
    asm("mov.b64 {%0,%1}, %2;" : "=f"(f.x), "=f"(f.y) : "l"(v));
    return f;
}
__device__ __forceinline__ unsigned long long ffma2(
    unsigned long long a, unsigned long long b, unsigned long long c) {
    unsigned long long d;
    asm("fma.rn.f32x2 %0, %1, %2, %3;" : "=l"(d) : "l"(a), "l"(b), "l"(c));
    return d;
}

// ---------------------------------------------------------------------------
// bilinear coefficients for output pixel (y,x) of the 50->100 upsample
// (align_corners=False; matches torch/jax reference)
// ---------------------------------------------------------------------------
__device__ __forceinline__ void bilin_coef(int y, int x,
                                           int& i00, int& i01, int& i10, int& i11,
                                           float& w00, float& w01,
                                           float& w10, float& w11) {
    float sy = 0.5f * (float)y - 0.25f;
    sy = fminf(fmaxf(sy, 0.0f), (float)(PHW - 1));
    int   y0 = (int)floorf(sy);
    float ty = sy - (float)y0;
    int   y1 = min(y0 + 1, PHW - 1);

    float sx = 0.5f * (float)x - 0.25f;
    sx = fminf(fmaxf(sx, 0.0f), (float)(PHW - 1));
    int   x0 = (int)floorf(sx);
    float tx = sx - (float)x0;
    int   x1 = min(x0 + 1, PHW - 1);

    i00 = y0 * PHW + x0;  i01 = y0 * PHW + x1;
    i10 = y1 * PHW + x0;  i11 = y1 * PHW + x1;
    w00 = (1.0f - ty) * (1.0f - tx);
    w01 = (1.0f - ty) * tx;
    w10 = ty * (1.0f - tx);
    w11 = ty * tx;
}

// ---------------------------------------------------------------------------
// Kernel 0c: transpose MLP weights into pair-packed layout:
// g_WT2[l][(c>>1)*256 + o] = {W[o*256+c], W[o*256+c+1]}
// ---------------------------------------------------------------------------
__global__ void __launch_bounds__(256) k_wtrans(
        const float* __restrict__ dW1, const float* __restrict__ dW2,
        const float* __restrict__ dW3, const float* __restrict__ rW1,
        const float* __restrict__ rW2, const float* __restrict__ rW3) {
    __shared__ float tile[32][33];
    int l = blockIdx.z;
    const float* W;
    switch (l) {
        case 0: W = dW1; break;
        case 1: W = dW2; break;
        case 2: W = dW3; break;
        case 3: W = rW1; break;
        case 4: W = rW2; break;
        default: W = rW3; break;
    }
    int oo = blockIdx.x * 32;    // output-row tile base
    int co = blockIdx.y * 32;    // input-col tile base
    int tx = threadIdx.x, ty = threadIdx.y;

#pragma unroll
    for (int k = 0; k < 4; k++) {
        int row = ty + 8 * k;    // o_local
        tile[row][tx] = W[(oo + row) * CH + (co + tx)];
    }
    __syncthreads();

    float2* dst = g_WT2 + l * ((CH / 2) * CH);
#pragma unroll
    for (int k = 0; k < 2; k++) {
        int c2l = ty + 8 * k;    // pair index within tile (0..15)
        float2 v = make_float2(tile[tx][2 * c2l], tile[tx][2 * c2l + 1]);
        dst[(co / 2 + c2l) * CH + (oo + tx)] = v;
    }
}

// ---------------------------------------------------------------------------
// shared helper: pack the 6 head-weight rows channel-major in smem
// ---------------------------------------------------------------------------
__device__ __forceinline__ void load_wpack(float (*wpack)[8],
                                           const float* __restrict__ Wc,
                                           const float* __restrict__ Wb,
                                           int tid) {
    if (tid < CH) {
        wpack[tid][0] = Wc[tid];
        wpack[tid][1] = Wc[CH + tid];
        wpack[tid][2] = Wb[tid];
        wpack[tid][3] = Wb[CH + tid];
        wpack[tid][4] = Wb[2 * CH + tid];
        wpack[tid][5] = Wb[3 * CH + tid];
        wpack[tid][6] = 0.f;
        wpack[tid][7] = 0.f;
    }
}

// ---------------------------------------------------------------------------
// Kernel 0b: g_posdot[n][j] = bias_j + sum_c pos[c][n] * Wrow_j[c]
// pos computed inline from pe (bilinear); pe is 2.5 MB -> L2-resident.
// ---------------------------------------------------------------------------
__global__ void __launch_bounds__(256) k_posdot(
        const float* __restrict__ pe,
        const float* __restrict__ Wc, const float* __restrict__ bc,
        const float* __restrict__ Wb, const float* __restrict__ bb) {
    __shared__ float wpack[CH][8];
    int tid = threadIdx.x;
    load_wpack(wpack, Wc, Wb, tid);
    __syncthreads();

    int n = blockIdx.x * blockDim.x + tid;
    if (n >= NPOS) return;

    int i00, i01, i10, i11;
    float w00, w01, w10, w11;
    bilin_coef(n / HPIX, n % HPIX, i00, i01, i10, i11, w00, w01, w10, w11);

    float acc0 = bc[0], acc1 = bc[1];
    float acc2 = bb[0], acc3 = bb[1], acc4 = bb[2], acc5 = bb[3];

#pragma unroll 4
    for (int c = 0; c < CH; c++) {
        const float* P = pe + c * (PHW * PHW);
        float p = P[i00] * w00 + P[i01] * w01 + P[i10] * w10 + P[i11] * w11;
        float4 w0 = *(const float4*)&wpack[c][0];
        float4 w1 = *(const float4*)&wpack[c][4];
        acc0 += p * w0.x; acc1 += p * w0.y;
        acc2 += p * w0.z; acc3 += p * w0.w;
        acc4 += p * w1.x; acc5 += p * w1.y;
    }
    float* dst = g_posdot + n * 6;
    dst[0] = acc0; dst[1] = acc1; dst[2] = acc2;
    dst[3] = acc3; dst[4] = acc4; dst[5] = acc5;
}

// ---------------------------------------------------------------------------
// Kernel A: main pass. Reads x once (163 MB, HBM-bound); cls/bbox to out.
// ---------------------------------------------------------------------------
__global__ void __launch_bounds__(256) k_heads(
        const float* __restrict__ X, const float* __restrict__ Wc,
        const float* __restrict__ Wb, float* __restrict__ out) {
    __shared__ float wpack[CH][8];
    int tid = threadIdx.x;
    load_wpack(wpack, Wc, Wb, tid);
    __syncthreads();

    int b = blockIdx.y;
    int n = blockIdx.x * blockDim.x + tid;
    if (n >= NPOS) return;

    const float* pd = g_posdot + n * 6;
    float acc0 = pd[0], acc1 = pd[1], acc2 = pd[2];
    float acc3 = pd[3], acc4 = pd[4], acc5 = pd[5];

    const float* xp = X + (size_t)b * (CH * NPOS) + n;
#pragma unroll 8
    for (int c = 0; c < CH; c++) {
        float xv = xp[(size_t)c * NPOS];
        float4 w0 = *(const float4*)&wpack[c][0];
        float4 w1 = *(const float4*)&wpack[c][4];
        acc0 += xv * w0.x; acc1 += xv * w0.y;
        acc2 += xv * w0.z; acc3 += xv * w0.w;
        acc4 += xv * w1.x; acc5 += xv * w1.y;
    }

    int bn = b * NPOS + n;
    *(float2*)&out[CLS_OFF + (size_t)bn * 2] = make_float2(acc0, acc1);
    *(float4*)&out[BBX_OFF + (size_t)bn * 4] = make_float4(acc2, acc3, acc4, acc5);
}

// ---------------------------------------------------------------------------
// Top-k via hierarchical bitonic sort on packed u64 keys
// key = ord_float(l1 - l0) << 32 | (0xFFFFFFFF - n)  — unique; descending
// sort reproduces jax.lax.top_k order (desc score, ties -> lower index).
// ---------------------------------------------------------------------------
__device__ __forceinline__ unsigned int ord_float(float f) {
    unsigned int b = __float_as_uint(f);
    return (b & 0x80000000u) ? ~b : (b | 0x80000000u);
}

// Phase 1: grid (NCHUNK, BATCH), 512 threads. Sort one 2000-element chunk
// (padded to 2048) descending; emit its sorted top-100 candidate keys.
// Any global top-100 element is inside its chunk's top-100 -> exact.
__global__ void __launch_bounds__(512) k_topk_local(const float* __restrict__ cls) {
    __shared__ unsigned long long key[CPAD];   // 16 KB
    int tid = threadIdx.x;
    int j = blockIdx.x, b = blockIdx.y;
    int base = j * CHUNKN;

    const float2* sp = (const float2*)(cls + (size_t)b * NPOS * 2);
#pragma unroll
    for (int i = tid; i < CPAD; i += 512) {
        int n = base + i;
        unsigned long long k = 0;
        if (i < CHUNKN && n < NPOS) {
            float2 l = sp[n];
            k = ((unsigned long long)ord_float(l.y - l.x) << 32) |
                (unsigned long long)(0xFFFFFFFFu - (unsigned int)n);
        }
        key[i] = k;
    }
    __syncthreads();

    // bitonic sort, descending
    for (int k = 2; k <= CPAD; k <<= 1) {
        for (int s = k >> 1; s > 0; s >>= 1) {
#pragma unroll
            for (int i = tid; i < CPAD; i += 512) {
                int ix = i ^ s;
                if (ix > i) {
                    unsigned long long a = key[i], c = key[ix];
                    bool desc = ((i & k) == 0);
                    if (desc ? (a < c) : (a > c)) { key[i] = c; key[ix] = a; }
                }
            }
            __syncthreads();
        }
    }

    if (tid < KDET)
        g_cand[(b * NCHUNK + j) * KDET + tid] = key[tid];
}

// Phase 2: grid BATCH, 512 threads. Sort the 500 candidates (padded to 512)
// descending; write the sorted top-100 indices.
__global__ void __launch_bounds__(512) k_topk_merge() {
    __shared__ unsigned long long key[MPAD];   // 4 KB
    int tid = threadIdx.x;
    int b = blockIdx.x;

    key[tid] = (tid < MERGEN) ? g_cand[b * MERGEN + tid] : 0ull;
    __syncthreads();

    for (int k = 2; k <= MPAD; k <<= 1) {
        for (int s = k >> 1; s > 0; s >>= 1) {
            int i = tid;
            int ix = i ^ s;
            if (ix > i) {
                unsigned long long a = key[i], c = key[ix];
                bool desc = ((i & k) == 0);
                if (desc ? (a < c) : (a > c)) { key[i] = c; key[ix] = a; }
            }
            __syncthreads();
        }
    }

    if (tid < KDET)
        g_idx[b * KDET + tid] =
            (int)(0xFFFFFFFFu - (unsigned int)(key[tid] & 0xFFFFFFFFull));
}

// ---------------------------------------------------------------------------
// Kernel C: gather selected features (x + pos) and run 3-layer MLP + query.
// Blocks 0..99 = det (16 rows each), 100..124 = rec (16 rows each).
// 256 threads; thread tid owns output neuron o = tid for ALL 16 rows.
// buf layout: buf[c*20 + r], r = 0..15 (stride-20 padding, 16B-aligned).
// ---------------------------------------------------------------------------
#define BUF_STRIDE 20

__device__ __forceinline__ void mlp_layer(float* __restrict__ buf,
                                          const float2* __restrict__ WT,
                                          const float* __restrict__ bias,
                                          bool relu, int o) {
    float bv = bias[o];
    unsigned long long a0 = pack2(bv, bv);
    unsigned long long a1 = a0, a2 = a0, a3 = a0;
    unsigned long long a4 = a0, a5 = a0, a6 = a0, a7 = a0;

    const float2* wp = WT + o;
#pragma unroll 2
    for (int c2 = 0; c2 < CH / 2; c2++) {
        float2 w2 = wp[c2 * CH];
        unsigned long long w0 = pack2(w2.x, w2.x);
        unsigned long long w1 = pack2(w2.y, w2.y);
        const float* base0 = buf + (2 * c2) * BUF_STRIDE;
        const float* base1 = buf + (2 * c2 + 1) * BUF_STRIDE;
        {   // channel 2*c2, rows 0..15
            ulonglong2 u0 = *(const ulonglong2*)(base0 + 0);
            ulonglong2 u1 = *(const ulonglong2*)(base0 + 4);
            ulonglong2 u2 = *(const ulonglong2*)(base0 + 8);
            ulonglong2 u3 = *(const ulonglong2*)(base0 + 12);
            a0 = ffma2(u0.x, w0, a0);  a1 = ffma2(u0.y, w0, a1);
            a2 = ffma2(u1.x, w0, a2);  a3 = ffma2(u1.y, w0, a3);
            a4 = ffma2(u2.x, w0, a4);  a5 = ffma2(u2.y, w0, a5);
            a6 = ffma2(u3.x, w0, a6);  a7 = ffma2(u3.y, w0, a7);
        }
        {   // channel 2*c2+1, rows 0..15
            ulonglong2 u0 = *(const ulonglong2*)(base1 + 0);
            ulonglong2 u1 = *(const ulonglong2*)(base1 + 4);
            ulonglong2 u2 = *(const ulonglong2*)(base1 + 8);
            ulonglong2 u3 = *(const ulonglong2*)(base1 + 12);
            a0 = ffma2(u0.x, w1, a0);  a1 = ffma2(u0.y, w1, a1);
            a2 = ffma2(u1.x, w1, a2);  a3 = ffma2(u1.y, w1, a3);
            a4 = ffma2(u2.x, w1, a4);  a5 = ffma2(u2.y, w1, a5);
            a6 = ffma2(u3.x, w1, a6);  a7 = ffma2(u3.y, w1, a7);
        }
    }
    __syncthreads();   // everyone done reading buf
    {
        float2 r0 = unpack2(a0), r1 = unpack2(a1);
        float2 r2 = unpack2(a2), r3 = unpack2(a3);
        float2 r4 = unpack2(a4), r5 = unpack2(a5);
        float2 r6 = unpack2(a6), r7 = unpack2(a7);
        if (relu) {
            r0.x = fmaxf(r0.x, 0.f); r0.y = fmaxf(r0.y, 0.f);
            r1.x = fmaxf(r1.x, 0.f); r1.y = fmaxf(r1.y, 0.f);
            r2.x = fmaxf(r2.x, 0.f); r2.y = fmaxf(r2.y, 0.f);
            r3.x = fmaxf(r3.x, 0.f); r3.y = fmaxf(r3.y, 0.f);
            r4.x = fmaxf(r4.x, 0.f); r4.y = fmaxf(r4.y, 0.f);
            r5.x = fmaxf(r5.x, 0.f); r5.y = fmaxf(r5.y, 0.f);
            r6.x = fmaxf(r6.x, 0.f); r6.y = fmaxf(r6.y, 0.f);
            r7.x = fmaxf(r7.x, 0.f); r7.y = fmaxf(r7.y, 0.f);
        }
        float* dst = buf + o * BUF_STRIDE;
        *(float2*)(dst + 0)  = r0;  *(float2*)(dst + 2)  = r1;
        *(float2*)(dst + 4)  = r2;  *(float2*)(dst + 6)  = r3;
        *(float2*)(dst + 8)  = r4;  *(float2*)(dst + 10) = r5;
        *(float2*)(dst + 12) = r6;  *(float2*)(dst + 14) = r7;
    }
    __syncthreads();   // buf ready for next layer
}

__global__ void __launch_bounds__(256) k_mlp(
        const float* __restrict__ X, const float* __restrict__ pe,
        const float* __restrict__ db1, const float* __restrict__ db2,
        const float* __restrict__ db3,
        const float* __restrict__ rb1, const float* __restrict__ rb2,
        const float* __restrict__ rb3,
        const float* __restrict__ det_q, const float* __restrict__ rec_q,
        float* __restrict__ out) {
    __shared__ float buf[CH * BUF_STRIDE];   // 20 KB
    __shared__ int   s_n[16], s_b[16], s_q[16];
    __shared__ int   s_i00[16], s_i01[16], s_i10[16], s_i11[16];
    __shared__ float s_w00[16], s_w01[16], s_w10[16], s_w11[16];

    int tid = threadIdx.x;
    int blk = blockIdx.x;
    bool isdet = (blk < 100);
    int rowbase = isdet ? blk * 16 : (blk - 100) * 16;

    if (tid < 16) {
        int row = rowbase + tid;
        int b, q;
        if (isdet) { b = row / KDET; q = row % KDET; }
        else       { b = row / KREC; q = row % KREC; }
        s_b[tid] = b;
        s_q[tid] = q;
        int n = g_idx[b * KDET + q];
        s_n[tid] = n;
        int i00, i01, i10, i11;
        float w00, w01, w10, w11;
        bilin_coef(n / HPIX, n % HPIX, i00, i01, i10, i11, w00, w01, w10, w11);
        s_i00[tid] = i00; s_i01[tid] = i01; s_i10[tid] = i10; s_i11[tid] = i11;
        s_w00[tid] = w00; s_w01[tid] = w01; s_w10[tid] = w10; s_w11[tid] = w11;
    }
    __syncthreads();

    // gather: buf[c*20 + r] = x[b,c,n] + pos(c,n)   (pos inlined from pe)
    {
        int c = tid;
        const float* P = pe + c * (PHW * PHW);
#pragma unroll 4
        for (int r = 0; r < 16; r++) {
            float pv = P[s_i00[r]] * s_w00[r] + P[s_i01[r]] * s_w01[r] +
                       P[s_i10[r]] * s_w10[r] + P[s_i11[r]] * s_w11[r];
            buf[c * BUF_STRIDE + r] =
                X[((size_t)s_b[r] * CH + c) * NPOS + s_n[r]] + pv;
        }
    }
    __syncthreads();

    const float *B1, *B2, *B3, *Q;
    const float2* WT = g_WT2 + (isdet ? 0 : 3) * ((CH / 2) * CH);
    if (isdet) { B1 = db1; B2 = db2; B3 = db3; Q = det_q; }
    else       { B1 = rb1; B2 = rb2; B3 = rb3; Q = rec_q; }

    mlp_layer(buf, WT,                     B1, true,  tid);
    mlp_layer(buf, WT + (CH / 2) * CH,     B2, true,  tid);
    mlp_layer(buf, WT + 2 * (CH / 2) * CH, B3, false, tid);

    // epilogue: add query embedding, write output
    {
        int c = tid;
#pragma unroll 4
        for (int r = 0; r < 16; r++) {
            int row = rowbase + r;
            float v = buf[c * BUF_STRIDE + r] + Q[s_q[r] * CH + c];
            size_t dst = isdet ? (DET_OFF + (size_t)row * CH + c)
                               : (REC_OFF + (size_t)row * CH + c);
            out[dst] = v;
        }
    }
}

// ---------------------------------------------------------------------------
// launch  (no static initializers, no attribute calls, no allocation APIs,
// no __device__ symbols passed as kernel arguments)
// ---------------------------------------------------------------------------
extern "C" void kernel_launch(void* const* d_in, const int* in_sizes, int n_in,
                              void* d_out, int out_size) {
    const float* X    = (const float*)d_in[0];
    const float* Wc   = (const float*)d_in[1];
    const float* bc   = (const float*)d_in[2];
    const float* Wb   = (const float*)d_in[3];
    const float* bb   = (const float*)d_in[4];
    const float* dW1  = (const float*)d_in[5];
    const float* db1  = (const float*)d_in[6];
    const float* dW2  = (const float*)d_in[7];
    const float* db2  = (const float*)d_in[8];
    const float* dW3  = (const float*)d_in[9];
    const float* db3  = (const float*)d_in[10];
    const float* rW1  = (const float*)d_in[11];
    const float* rb1  = (const float*)d_in[12];
    const float* rW2  = (const float*)d_in[13];
    const float* rb2  = (const float*)d_in[14];
    const float* rW3  = (const float*)d_in[15];
    const float* rb3  = (const float*)d_in[16];
    const float* detq = (const float*)d_in[17];
    const float* recq = (const float*)d_in[18];
    const float* pe   = (const float*)d_in[19];
    float* out = (float*)d_out;

    // 0b: pos-dot precompute (folds pos out of the hot pass; pos inlined)
    k_posdot<<<(NPOS + 255) / 256, 256>>>(pe, Wc, bc, Wb, bb);
    // 0c: pack/transpose MLP weights
    {
        dim3 grid(CH / 32, CH / 32, 6);
        dim3 blockd(32, 8);
        k_wtrans<<<grid, blockd>>>(dW1, dW2, dW3, rW1, rW2, rW3);
    }
    // A: heads (HBM-bound main pass; writes cls+bbox into out)
    {
        dim3 grid((NPOS + 255) / 256, BATCH);
        k_heads<<<grid, 256>>>(X, Wc, Wb, out);
    }
    // B: exact sorted top-100 per batch — hierarchical bitonic sort
    {
        dim3 grid1(NCHUNK, BATCH);
        k_topk_local<<<grid1, 512>>>(out + CLS_OFF);
        k_topk_merge<<<BATCH, 512>>>();
    }
    // C: gather + MLPs + queries
    k_mlp<<<125, 256>>>(X, pe, db1, db2, db3, rb1, rb2, rb3, detq, recq, out);
}

// round 13
// speedup vs baseline: 1.5094x; 1.1727x over previous
#include <cuda_runtime.h>
#include <cuda_bf16.h>

// ---------------------------------------------------------------------------
// QueryInitialization: pos-resize + det/cls heads + top-k + query MLPs
// B=16, C=256, H=W=100 (N=10000), pos 50x50, det_k=100, rec_k=25
// Outputs concatenated: det[16,100,256] | rec[16,25,256] |
//                       cls[16,10000,2] | bbox[16,10000,4]
// ---------------------------------------------------------------------------

#define BATCH 16
#define CH    256
#define NPOS  10000
#define HPIX  100
#define PHW   50
#define KDET  100
#define KREC  25

#define DET_OFF  0
#define REC_OFF  (BATCH*KDET*CH)                 // 409600
#define CLS_OFF  (REC_OFF + BATCH*KREC*CH)       // 512000
#define BBX_OFF  (CLS_OFF + BATCH*NPOS*2)        // 832000

// top-k chunking: 10 chunks x 1000 elements (padded to 1024 for bitonic)
#define NCHUNK  10
#define CHUNKN  1000
#define CPAD    1024
#define CANDN   (NCHUNK * KDET)   // 1000 candidates per batch

// k_pre grid split: wtrans blocks then posdot blocks
#define WT_BLOCKS  (8 * 8 * 6)            // 384
#define PD_BLOCKS  ((NPOS + 255) / 256)   // 40
#define PRE_BLOCKS (WT_BLOCKS + PD_BLOCKS)

// scratch (__device__ globals, accessed ONLY from device code — never passed
// as host-side kernel arguments: that hands the kernel the host shadow
// address, which ATS on the Grace host silently services -> UVM pool growth
// -> harness memory violation. Root cause of rounds 1-8.)
__device__ float  g_posdot[NPOS * 6];                // pos@[Wc;Wb]^T + bias
__device__ int    g_idx[BATCH * KDET];               // sorted top-100 / batch
__device__ float2 g_WT2[6 * (CH / 2) * CH];          // packed MLP weights
__device__ unsigned long long g_cand[BATCH * CANDN]; // chunk top-100 keys
__device__ unsigned int g_done[BATCH];               // topk arrival counters

// ---------------------------------------------------------------------------
// f32x2 packed helpers (Blackwell FFMA2)
// ---------------------------------------------------------------------------
__device__ __forceinline__ unsigned long long pack2(float x, float y) {
    unsigned long long r;
    asm("mov.b64 %0, {%1,%2};" : "=l"(r) : "f"(x), "f"(y));
    return r;
}
__device__ __forceinline__ float2 unpack2(unsigned long long v) {
    float2 f;
    asm("mov.b64 {%0,%1}, %2;" : "=f"(f.x), "=f"(f.y) : "l"(v));
    return f;
}
__device__ __forceinline__ unsigned long long ffma2(
    unsigned long long a, unsigned long long b, unsigned long long c) {
    unsigned long long d;
    asm("fma.rn.f32x2 %0, %1, %2, %3;" : "=l"(d) : "l"(a), "l"(b), "l"(c));
    return d;
}

// ---------------------------------------------------------------------------
// bilinear coefficients for output pixel (y,x) of the 50->100 upsample
// (align_corners=False; matches torch/jax reference)
// ---------------------------------------------------------------------------
__device__ __forceinline__ void bilin_coef(int y, int x,
                                           int& i00, int& i01, int& i10, int& i11,
                                           float& w00, float& w01,
                                           float& w10, float& w11) {
    float sy = 0.5f * (float)y - 0.25f;
    sy = fminf(fmaxf(sy, 0.0f), (float)(PHW - 1));
    int   y0 = (int)floorf(sy);
    float ty = sy - (float)y0;
    int   y1 = min(y0 + 1, PHW - 1);

    float sx = 0.5f * (float)x - 0.25f;
    sx = fminf(fmaxf(sx, 0.0f), (float)(PHW - 1));
    int   x0 = (int)floorf(sx);
    float tx = sx - (float)x0;
    int   x1 = min(x0 + 1, PHW - 1);

    i00 = y0 * PHW + x0;  i01 = y0 * PHW + x1;
    i10 = y1 * PHW + x0;  i11 = y1 * PHW + x1;
    w00 = (1.0f - ty) * (1.0f - tx);
    w01 = (1.0f - ty) * tx;
    w10 = ty * (1.0f - tx);
    w11 = ty * tx;
}

// ---------------------------------------------------------------------------
// Kernel PRE (fused): weight transpose + posdot precompute + counter reset.
// Blocks [0, 384): transpose MLP weights into pair-packed layout
//   g_WT2[l][(c>>1)*256 + o] = {W[o*256+c], W[o*256+c+1]}
// Blocks [384, 424): g_posdot[n][j] = bias_j + sum_c pos[c][n] * Wrow_j[c]
// Block 0 additionally resets g_done (graph-replay safe: runs before k_topk).
// ---------------------------------------------------------------------------
__global__ void __launch_bounds__(256) k_pre(
        const float* __restrict__ pe,
        const float* __restrict__ Wc, const float* __restrict__ bc,
        const float* __restrict__ Wb, const float* __restrict__ bb,
        const float* __restrict__ dW1, const float* __restrict__ dW2,
        const float* __restrict__ dW3, const float* __restrict__ rW1,
        const float* __restrict__ rW2, const float* __restrict__ rW3) {
    __shared__ float tile[32][33];
    __shared__ float wpack[CH][8];

    int blk = blockIdx.x;
    int tid = threadIdx.x;

    if (blk == 0 && tid < BATCH) g_done[tid] = 0;

    if (blk < WT_BLOCKS) {
        // ---- weight transpose ----
        int l   = blk / 64;
        int rem = blk % 64;
        int oo  = (rem / 8) * 32;    // output-row tile base
        int co  = (rem % 8) * 32;    // input-col tile base
        int tx = tid % 32, ty = tid / 32;

        const float* W;
        switch (l) {
            case 0: W = dW1; break;
            case 1: W = dW2; break;
            case 2: W = dW3; break;
            case 3: W = rW1; break;
            case 4: W = rW2; break;
            default: W = rW3; break;
        }

#pragma unroll
        for (int k = 0; k < 4; k++) {
            int row = ty + 8 * k;    // o_local
            tile[row][tx] = W[(oo + row) * CH + (co + tx)];
        }
        __syncthreads();

        float2* dst = g_WT2 + l * ((CH / 2) * CH);
#pragma unroll
        for (int k = 0; k < 2; k++) {
            int c2l = ty + 8 * k;    // pair index within tile (0..15)
            float2 v = make_float2(tile[tx][2 * c2l], tile[tx][2 * c2l + 1]);
            dst[(co / 2 + c2l) * CH + (oo + tx)] = v;
        }
        return;
    }

    // ---- posdot ----
    if (tid < CH) {
        wpack[tid][0] = Wc[tid];
        wpack[tid][1] = Wc[CH + tid];
        wpack[tid][2] = Wb[tid];
        wpack[tid][3] = Wb[CH + tid];
        wpack[tid][4] = Wb[2 * CH + tid];
        wpack[tid][5] = Wb[3 * CH + tid];
        wpack[tid][6] = 0.f;
        wpack[tid][7] = 0.f;
    }
    __syncthreads();

    int n = (blk - WT_BLOCKS) * 256 + tid;
    if (n >= NPOS) return;

    int i00, i01, i10, i11;
    float w00, w01, w10, w11;
    bilin_coef(n / HPIX, n % HPIX, i00, i01, i10, i11, w00, w01, w10, w11);

    float acc0 = bc[0], acc1 = bc[1];
    float acc2 = bb[0], acc3 = bb[1], acc4 = bb[2], acc5 = bb[3];

#pragma unroll 8
    for (int c = 0; c < CH; c++) {
        const float* P = pe + c * (PHW * PHW);
        float p = P[i00] * w00 + P[i01] * w01 + P[i10] * w10 + P[i11] * w11;
        float4 w0 = *(const float4*)&wpack[c][0];
        float4 w1 = *(const float4*)&wpack[c][4];
        acc0 += p * w0.x; acc1 += p * w0.y;
        acc2 += p * w0.z; acc3 += p * w0.w;
        acc4 += p * w1.x; acc5 += p * w1.y;
    }
    float* dst = g_posdot + n * 6;
    dst[0] = acc0; dst[1] = acc1; dst[2] = acc2;
    dst[3] = acc3; dst[4] = acc4; dst[5] = acc5;
}

// ---------------------------------------------------------------------------
// Kernel A: main pass. Reads x once (163 MB, HBM-bound) with streaming
// (__ldcs, evict-first: zero reuse) and streams cls/bbox out (__stcs).
// ---------------------------------------------------------------------------
__global__ void __launch_bounds__(256) k_heads(
        const float* __restrict__ X, const float* __restrict__ Wc,
        const float* __restrict__ Wb, float* __restrict__ out) {
    __shared__ float wpack[CH][8];
    int tid = threadIdx.x;
    if (tid < CH) {
        wpack[tid][0] = Wc[tid];
        wpack[tid][1] = Wc[CH + tid];
        wpack[tid][2] = Wb[tid];
        wpack[tid][3] = Wb[CH + tid];
        wpack[tid][4] = Wb[2 * CH + tid];
        wpack[tid][5] = Wb[3 * CH + tid];
        wpack[tid][6] = 0.f;
        wpack[tid][7] = 0.f;
    }
    __syncthreads();

    int b = blockIdx.y;
    int n = blockIdx.x * blockDim.x + tid;
    if (n >= NPOS) return;

    const float* pd = g_posdot + n * 6;
    float acc0 = pd[0], acc1 = pd[1], acc2 = pd[2];
    float acc3 = pd[3], acc4 = pd[4], acc5 = pd[5];

    const float* xp = X + (size_t)b * (CH * NPOS) + n;
#pragma unroll 8
    for (int c = 0; c < CH; c++) {
        float xv = __ldcs(xp + (size_t)c * NPOS);
        float4 w0 = *(const float4*)&wpack[c][0];
        float4 w1 = *(const float4*)&wpack[c][4];
        acc0 += xv * w0.x; acc1 += xv * w0.y;
        acc2 += xv * w0.z; acc3 += xv * w0.w;
        acc4 += xv * w1.x; acc5 += xv * w1.y;
    }

    int bn = b * NPOS + n;
    __stcs((float2*)&out[CLS_OFF + (size_t)bn * 2], make_float2(acc0, acc1));
    __stcs((float4*)&out[BBX_OFF + (size_t)bn * 4],
           make_float4(acc2, acc3, acc4, acc5));
}

// ---------------------------------------------------------------------------
// Kernel B (fused): top-100 per batch, exact jax.lax.top_k order.
// grid (NCHUNK, BATCH), 512 threads. Each block bitonic-sorts its 1000-element
// chunk (pad 1024) descending on packed u64 keys and emits its top-100.
// The LAST block per batch (atomic counter) then merges that batch's 1000
// candidates (pad 1024, second bitonic) and writes the sorted top-100 indices.
// key = ord_float(l1-l0)<<32 | (0xFFFFFFFF-n): unique; descending sort
// reproduces jax order (desc score, ties -> lower index).
// ---------------------------------------------------------------------------
__device__ __forceinline__ unsigned int ord_float(float f) {
    unsigned int b = __float_as_uint(f);
    return (b & 0x80000000u) ? ~b : (b | 0x80000000u);
}

__device__ __forceinline__ void bitonic_desc_1024(unsigned long long* key, int tid) {
    for (int k = 2; k <= CPAD; k <<= 1) {
        for (int s = k >> 1; s > 0; s >>= 1) {
#pragma unroll
            for (int i = tid; i < CPAD; i += 512) {
                int ix = i ^ s;
                if (ix > i) {
                    unsigned long long a = key[i], c = key[ix];
                    bool desc = ((i & k) == 0);
                    if (desc ? (a < c) : (a > c)) { key[i] = c; key[ix] = a; }
                }
            }
            __syncthreads();
        }
    }
}

__global__ void __launch_bounds__(512) k_topk(const float* __restrict__ cls) {
    __shared__ unsigned long long key[CPAD];   // 8 KB
    __shared__ int s_last;
    int tid = threadIdx.x;
    int j = blockIdx.x, b = blockIdx.y;

    const float2* sp = (const float2*)(cls + (size_t)b * NPOS * 2);
#pragma unroll
    for (int i = tid; i < CPAD; i += 512) {
        int n = j * CHUNKN + i;
        unsigned long long k = 0;
        if (i < CHUNKN) {
            float2 l = sp[n];
            k = ((unsigned long long)ord_float(l.y - l.x) << 32) |
                (unsigned long long)(0xFFFFFFFFu - (unsigned int)n);
        }
        key[i] = k;
    }
    __syncthreads();

    bitonic_desc_1024(key, tid);

    if (tid < KDET)
        g_cand[b * CANDN + j * KDET + tid] = key[tid];
    __threadfence();
    __syncthreads();

    if (tid == 0)
        s_last = (atomicAdd(&g_done[b], 1u) == NCHUNK - 1) ? 1 : 0;
    __syncthreads();
    if (!s_last) return;
    __threadfence();   // acquire: see all chunks' g_cand writes

    // merge: sort this batch's 1000 candidates (pad 1024), emit top-100
#pragma unroll
    for (int i = tid; i < CPAD; i += 512)
        key[i] = (i < CANDN) ? g_cand[b * CANDN + i] : 0ull;
    __syncthreads();

    bitonic_desc_1024(key, tid);

    if (tid < KDET)
        g_idx[b * KDET + tid] =
            (int)(0xFFFFFFFFu - (unsigned int)(key[tid] & 0xFFFFFFFFull));
}

// ---------------------------------------------------------------------------
// Kernel C: gather selected features (x + pos) and run 3-layer MLP + query.
// Blocks 0..99 = det (16 rows each), 100..124 = rec (16 rows each).
// 256 threads; thread tid owns output neuron o = tid for ALL 16 rows.
// buf layout: buf[c*20 + r], r = 0..15 (stride-20 padding, 16B-aligned).
// ---------------------------------------------------------------------------
#define BUF_STRIDE 20

__device__ __forceinline__ void mlp_layer(float* __restrict__ buf,
                                          const float2* __restrict__ WT,
                                          const float* __restrict__ bias,
                                          bool relu, int o) {
    float bv = bias[o];
    unsigned long long a0 = pack2(bv, bv);
    unsigned long long a1 = a0, a2 = a0, a3 = a0;
    unsigned long long a4 = a0, a5 = a0, a6 = a0, a7 = a0;

    const float2* wp = WT + o;
#pragma unroll 2
    for (int c2 = 0; c2 < CH / 2; c2++) {
        float2 w2 = wp[c2 * CH];
        unsigned long long w0 = pack2(w2.x, w2.x);
        unsigned long long w1 = pack2(w2.y, w2.y);
        const float* base0 = buf + (2 * c2) * BUF_STRIDE;
        const float* base1 = buf + (2 * c2 + 1) * BUF_STRIDE;
        {   // channel 2*c2, rows 0..15
            ulonglong2 u0 = *(const ulonglong2*)(base0 + 0);
            ulonglong2 u1 = *(const ulonglong2*)(base0 + 4);
            ulonglong2 u2 = *(const ulonglong2*)(base0 + 8);
            ulonglong2 u3 = *(const ulonglong2*)(base0 + 12);
            a0 = ffma2(u0.x, w0, a0);  a1 = ffma2(u0.y, w0, a1);
            a2 = ffma2(u1.x, w0, a2);  a3 = ffma2(u1.y, w0, a3);
            a4 = ffma2(u2.x, w0, a4);  a5 = ffma2(u2.y, w0, a5);
            a6 = ffma2(u3.x, w0, a6);  a7 = ffma2(u3.y, w0, a7);
        }
        {   // channel 2*c2+1, rows 0..15
            ulonglong2 u0 = *(const ulonglong2*)(base1 + 0);
            ulonglong2 u1 = *(const ulonglong2*)(base1 + 4);
            ulonglong2 u2 = *(const ulonglong2*)(base1 + 8);
            ulonglong2 u3 = *(const ulonglong2*)(base1 + 12);
            a0 = ffma2(u0.x, w1, a0);  a1 = ffma2(u0.y, w1, a1);
            a2 = ffma2(u1.x, w1, a2);  a3 = ffma2(u1.y, w1, a3);
            a4 = ffma2(u2.x, w1, a4);  a5 = ffma2(u2.y, w1, a5);
            a6 = ffma2(u3.x, w1, a6);  a7 = ffma2(u3.y, w1, a7);
        }
    }
    __syncthreads();   // everyone done reading buf
    {
        float2 r0 = unpack2(a0), r1 = unpack2(a1);
        float2 r2 = unpack2(a2), r3 = unpack2(a3);
        float2 r4 = unpack2(a4), r5 = unpack2(a5);
        float2 r6 = unpack2(a6), r7 = unpack2(a7);
        if (relu) {
            r0.x = fmaxf(r0.x, 0.f); r0.y = fmaxf(r0.y, 0.f);
            r1.x = fmaxf(r1.x, 0.f); r1.y = fmaxf(r1.y, 0.f);
            r2.x = fmaxf(r2.x, 0.f); r2.y = fmaxf(r2.y, 0.f);
            r3.x = fmaxf(r3.x, 0.f); r3.y = fmaxf(r3.y, 0.f);
            r4.x = fmaxf(r4.x, 0.f); r4.y = fmaxf(r4.y, 0.f);
            r5.x = fmaxf(r5.x, 0.f); r5.y = fmaxf(r5.y, 0.f);
            r6.x = fmaxf(r6.x, 0.f); r6.y = fmaxf(r6.y, 0.f);
            r7.x = fmaxf(r7.x, 0.f); r7.y = fmaxf(r7.y, 0.f);
        }
        float* dst = buf + o * BUF_STRIDE;
        *(float2*)(dst + 0)  = r0;  *(float2*)(dst + 2)  = r1;
        *(float2*)(dst + 4)  = r2;  *(float2*)(dst + 6)  = r3;
        *(float2*)(dst + 8)  = r4;  *(float2*)(dst + 10) = r5;
        *(float2*)(dst + 12) = r6;  *(float2*)(dst + 14) = r7;
    }
    __syncthreads();   // buf ready for next layer
}

__global__ void __launch_bounds__(256) k_mlp(
        const float* __restrict__ X, const float* __restrict__ pe,
        const float* __restrict__ db1, const float* __restrict__ db2,
        const float* __restrict__ db3,
        const float* __restrict__ rb1, const float* __restrict__ rb2,
        const float* __restrict__ rb3,
        const float* __restrict__ det_q, const float* __restrict__ rec_q,
        float* __restrict__ out) {
    __shared__ float buf[CH * BUF_STRIDE];   // 20 KB
    __shared__ int   s_n[16], s_b[16], s_q[16];
    __shared__ int   s_i00[16], s_i01[16], s_i10[16], s_i11[16];
    __shared__ float s_w00[16], s_w01[16], s_w10[16], s_w11[16];

    int tid = threadIdx.x;
    int blk = blockIdx.x;
    bool isdet = (blk < 100);
    int rowbase = isdet ? blk * 16 : (blk - 100) * 16;

    if (tid < 16) {
        int row = rowbase + tid;
        int b, q;
        if (isdet) { b = row / KDET; q = row % KDET; }
        else       { b = row / KREC; q = row % KREC; }
        s_b[tid] = b;
        s_q[tid] = q;
        int n = g_idx[b * KDET + q];
        s_n[tid] = n;
        int i00, i01, i10, i11;
        float w00, w01, w10, w11;
        bilin_coef(n / HPIX, n % HPIX, i00, i01, i10, i11, w00, w01, w10, w11);
        s_i00[tid] = i00; s_i01[tid] = i01; s_i10[tid] = i10; s_i11[tid] = i11;
        s_w00[tid] = w00; s_w01[tid] = w01; s_w10[tid] = w10; s_w11[tid] = w11;
    }
    __syncthreads();

    // gather: buf[c*20 + r] = x[b,c,n] + pos(c,n)   (pos inlined from pe)
    {
        int c = tid;
        const float* P = pe + c * (PHW * PHW);
#pragma unroll 4
        for (int r = 0; r < 16; r++) {
            float pv = P[s_i00[r]] * s_w00[r] + P[s_i01[r]] * s_w01[r] +
                       P[s_i10[r]] * s_w10[r] + P[s_i11[r]] * s_w11[r];
            buf[c * BUF_STRIDE + r] =
                X[((size_t)s_b[r] * CH + c) * NPOS + s_n[r]] + pv;
        }
    }
    __syncthreads();

    const float *B1, *B2, *B3, *Q;
    const float2* WT = g_WT2 + (isdet ? 0 : 3) * ((CH / 2) * CH);
    if (isdet) { B1 = db1; B2 = db2; B3 = db3; Q = det_q; }
    else       { B1 = rb1; B2 = rb2; B3 = rb3; Q = rec_q; }

    mlp_layer(buf, WT,                     B1, true,  tid);
    mlp_layer(buf, WT + (CH / 2) * CH,     B2, true,  tid);
    mlp_layer(buf, WT + 2 * (CH / 2) * CH, B3, false, tid);

    // epilogue: add query embedding, write output
    {
        int c = tid;
#pragma unroll 4
        for (int r = 0; r < 16; r++) {
            int row = rowbase + r;
            float v = buf[c * BUF_STRIDE + r] + Q[s_q[r] * CH + c];
            size_t dst = isdet ? (DET_OFF + (size_t)row * CH + c)
                               : (REC_OFF + (size_t)row * CH + c);
            out[dst] = v;
        }
    }
}

// ---------------------------------------------------------------------------
// launch  (4 kernels; no static initializers, no attribute calls, no
// allocation APIs, no __device__ symbols passed as kernel arguments)
// ---------------------------------------------------------------------------
extern "C" void kernel_launch(void* const* d_in, const int* in_sizes, int n_in,
                              void* d_out, int out_size) {
    const float* X    = (const float*)d_in[0];
    const float* Wc   = (const float*)d_in[1];
    const float* bc   = (const float*)d_in[2];
    const float* Wb   = (const float*)d_in[3];
    const float* bb   = (const float*)d_in[4];
    const float* dW1  = (const float*)d_in[5];
    const float* db1  = (const float*)d_in[6];
    const float* dW2  = (const float*)d_in[7];
    const float* db2  = (const float*)d_in[8];
    const float* dW3  = (const float*)d_in[9];
    const float* db3  = (const float*)d_in[10];
    const float* rW1  = (const float*)d_in[11];
    const float* rb1  = (const float*)d_in[12];
    const float* rW2  = (const float*)d_in[13];
    const float* rb2  = (const float*)d_in[14];
    const float* rW3  = (const float*)d_in[15];
    const float* rb3  = (const float*)d_in[16];
    const float* detq = (const float*)d_in[17];
    const float* recq = (const float*)d_in[18];
    const float* pe   = (const float*)d_in[19];
    float* out = (float*)d_out;

    // PRE: weight transpose + posdot + counter reset (fused)
    k_pre<<<PRE_BLOCKS, 256>>>(pe, Wc, bc, Wb, bb,
                               dW1, dW2, dW3, rW1, rW2, rW3);
    // A: heads (HBM-bound main pass; writes cls+bbox into out)
    {
        dim3 grid((NPOS + 255) / 256, BATCH);
        k_heads<<<grid, 256>>>(X, Wc, Wb, out);
    }
    // B: fused top-100 (local sorts + last-block merge per batch)
    {
        dim3 grid1(NCHUNK, BATCH);
        k_topk<<<grid1, 512>>>(out + CLS_OFF);
    }
    // C: gather + MLPs + queries
    k_mlp<<<125, 256>>>(X, pe, db1, db2, db3, rb1, rb2, rb3, detq, recq, out);
}

// round 14
// speedup vs baseline: 1.8736x; 1.2413x over previous
#include <cuda_runtime.h>
#include <cuda_bf16.h>

// ---------------------------------------------------------------------------
// QueryInitialization: pos-resize + det/cls heads + top-k + query MLPs
// B=16, C=256, H=W=100 (N=10000), pos 50x50, det_k=100, rec_k=25
// Outputs concatenated: det[16,100,256] | rec[16,25,256] |
//                       cls[16,10000,2] | bbox[16,10000,4]
// ---------------------------------------------------------------------------

#define BATCH 16
#define CH    256
#define NPOS  10000
#define HPIX  100
#define PHW   50
#define KDET  100
#define KREC  25

#define DET_OFF  0
#define REC_OFF  (BATCH*KDET*CH)                 // 409600
#define CLS_OFF  (REC_OFF + BATCH*KREC*CH)       // 512000
#define BBX_OFF  (CLS_OFF + BATCH*NPOS*2)        // 832000

// top-k chunking: 10 chunks x 1000 elements (padded to 1024 for bitonic)
#define NCHUNK  10
#define CHUNKN  1000
#define CPAD    1024
#define CANDN   (NCHUNK * KDET)   // 1000 candidates per batch

// k_pre grid split: wtrans blocks then posdot blocks
#define WT_BLOCKS  (8 * 8 * 6)            // 384
#define PD_BLOCKS  ((NPOS + 255) / 256)   // 40
#define PRE_BLOCKS (WT_BLOCKS + PD_BLOCKS)

// scratch (__device__ globals, accessed ONLY from device code — never passed
// as host-side kernel arguments: that hands the kernel the host shadow
// address, which ATS on the Grace host silently services -> UVM pool growth
// -> harness memory violation. Root cause of rounds 1-8.)
__device__ float  g_posdot[NPOS * 6];                // pos@[Wc;Wb]^T + bias
__device__ int    g_idx[BATCH * KDET];               // sorted top-100 / batch
__device__ float2 g_WT2[6 * (CH / 2) * CH];          // packed MLP weights
__device__ unsigned long long g_cand[BATCH * CANDN]; // chunk top-100 keys
__device__ unsigned int g_done[BATCH];               // topk arrival counters

// ---------------------------------------------------------------------------
// f32x2 packed helpers (Blackwell FFMA2)
// ---------------------------------------------------------------------------
__device__ __forceinline__ unsigned long long pack2(float x, float y) {
    unsigned long long r;
    asm("mov.b64 %0, {%1,%2};" : "=l"(r) : "f"(x), "f"(y));
    return r;
}
__device__ __forceinline__ float2 unpack2(unsigned long long v) {
    float2 f;
    asm("mov.b64 {%0,%1}, %2;" : "=f"(f.x), "=f"(f.y) : "l"(v));
    return f;
}
__device__ __forceinline__ unsigned long long ffma2(
    unsigned long long a, unsigned long long b, unsigned long long c) {
    unsigned long long d;
    asm("fma.rn.f32x2 %0, %1, %2, %3;" : "=l"(d) : "l"(a), "l"(b), "l"(c));
    return d;
}

// ---------------------------------------------------------------------------
// bilinear coefficients for output pixel (y,x) of the 50->100 upsample
// (align_corners=False; matches torch/jax reference)
// ---------------------------------------------------------------------------
__device__ __forceinline__ void bilin_coef(int y, int x,
                                           int& i00, int& i01, int& i10, int& i11,
                                           float& w00, float& w01,
                                           float& w10, float& w11) {
    float sy = 0.5f * (float)y - 0.25f;
    sy = fminf(fmaxf(sy, 0.0f), (float)(PHW - 1));
    int   y0 = (int)floorf(sy);
    float ty = sy - (float)y0;
    int   y1 = min(y0 + 1, PHW - 1);

    float sx = 0.5f * (float)x - 0.25f;
    sx = fminf(fmaxf(sx, 0.0f), (float)(PHW - 1));
    int   x0 = (int)floorf(sx);
    float tx = sx - (float)x0;
    int   x1 = min(x0 + 1, PHW - 1);

    i00 = y0 * PHW + x0;  i01 = y0 * PHW + x1;
    i10 = y1 * PHW + x0;  i11 = y1 * PHW + x1;
    w00 = (1.0f - ty) * (1.0f - tx);
    w01 = (1.0f - ty) * tx;
    w10 = ty * (1.0f - tx);
    w11 = ty * tx;
}

// ---------------------------------------------------------------------------
// Kernel PRE (fused): weight transpose + posdot precompute + counter reset.
// Blocks [0, 384): transpose MLP weights into pair-packed layout
//   g_WT2[l][(c>>1)*256 + o] = {W[o*256+c], W[o*256+c+1]}
// Blocks [384, 424): g_posdot[n][j] = bias_j + sum_c pos[c][n] * Wrow_j[c]
// Block 0 additionally resets g_done (graph-replay safe: runs before k_topk).
// ---------------------------------------------------------------------------
__global__ void __launch_bounds__(256) k_pre(
        const float* __restrict__ pe,
        const float* __restrict__ Wc, const float* __restrict__ bc,
        const float* __restrict__ Wb, const float* __restrict__ bb,
        const float* __restrict__ dW1, const float* __restrict__ dW2,
        const float* __restrict__ dW3, const float* __restrict__ rW1,
        const float* __restrict__ rW2, const float* __restrict__ rW3) {
    __shared__ float tile[32][33];
    __shared__ float wpack[CH][8];

    int blk = blockIdx.x;
    int tid = threadIdx.x;

    if (blk == 0 && tid < BATCH) g_done[tid] = 0;

    if (blk < WT_BLOCKS) {
        // ---- weight transpose ----
        int l   = blk / 64;
        int rem = blk % 64;
        int oo  = (rem / 8) * 32;    // output-row tile base
        int co  = (rem % 8) * 32;    // input-col tile base
        int tx = tid % 32, ty = tid / 32;

        const float* W;
        switch (l) {
            case 0: W = dW1; break;
            case 1: W = dW2; break;
            case 2: W = dW3; break;
            case 3: W = rW1; break;
            case 4: W = rW2; break;
            default: W = rW3; break;
        }

#pragma unroll
        for (int k = 0; k < 4; k++) {
            int row = ty + 8 * k;    // o_local
            tile[row][tx] = W[(oo + row) * CH + (co + tx)];
        }
        __syncthreads();

        float2* dst = g_WT2 + l * ((CH / 2) * CH);
#pragma unroll
        for (int k = 0; k < 2; k++) {
            int c2l = ty + 8 * k;    // pair index within tile (0..15)
            float2 v = make_float2(tile[tx][2 * c2l], tile[tx][2 * c2l + 1]);
            dst[(co / 2 + c2l) * CH + (oo + tx)] = v;
        }
        return;
    }

    // ---- posdot ----
    if (tid < CH) {
        wpack[tid][0] = Wc[tid];
        wpack[tid][1] = Wc[CH + tid];
        wpack[tid][2] = Wb[tid];
        wpack[tid][3] = Wb[CH + tid];
        wpack[tid][4] = Wb[2 * CH + tid];
        wpack[tid][5] = Wb[3 * CH + tid];
        wpack[tid][6] = 0.f;
        wpack[tid][7] = 0.f;
    }
    __syncthreads();

    int n = (blk - WT_BLOCKS) * 256 + tid;
    if (n >= NPOS) return;

    int i00, i01, i10, i11;
    float w00, w01, w10, w11;
    bilin_coef(n / HPIX, n % HPIX, i00, i01, i10, i11, w00, w01, w10, w11);

    float acc0 = bc[0], acc1 = bc[1];
    float acc2 = bb[0], acc3 = bb[1], acc4 = bb[2], acc5 = bb[3];

#pragma unroll 8
    for (int c = 0; c < CH; c++) {
        const float* P = pe + c * (PHW * PHW);
        float p = P[i00] * w00 + P[i01] * w01 + P[i10] * w10 + P[i11] * w11;
        float4 w0 = *(const float4*)&wpack[c][0];
        float4 w1 = *(const float4*)&wpack[c][4];
        acc0 += p * w0.x; acc1 += p * w0.y;
        acc2 += p * w0.z; acc3 += p * w0.w;
        acc4 += p * w1.x; acc5 += p * w1.y;
    }
    float* dst = g_posdot + n * 6;
    dst[0] = acc0; dst[1] = acc1; dst[2] = acc2;
    dst[3] = acc3; dst[4] = acc4; dst[5] = acc5;
}

// ---------------------------------------------------------------------------
// Kernel A: main pass. Reads x once (163 MB, HBM-bound) with streaming
// (__ldcs, evict-first: zero reuse) and streams cls/bbox out (__stcs).
// ---------------------------------------------------------------------------
__global__ void __launch_bounds__(256) k_heads(
        const float* __restrict__ X, const float* __restrict__ Wc,
        const float* __restrict__ Wb, float* __restrict__ out) {
    __shared__ float wpack[CH][8];
    int tid = threadIdx.x;
    if (tid < CH) {
        wpack[tid][0] = Wc[tid];
        wpack[tid][1] = Wc[CH + tid];
        wpack[tid][2] = Wb[tid];
        wpack[tid][3] = Wb[CH + tid];
        wpack[tid][4] = Wb[2 * CH + tid];
        wpack[tid][5] = Wb[3 * CH + tid];
        wpack[tid][6] = 0.f;
        wpack[tid][7] = 0.f;
    }
    __syncthreads();

    int b = blockIdx.y;
    int n = blockIdx.x * blockDim.x + tid;
    if (n >= NPOS) return;

    const float* pd = g_posdot + n * 6;
    float acc0 = pd[0], acc1 = pd[1], acc2 = pd[2];
    float acc3 = pd[3], acc4 = pd[4], acc5 = pd[5];

    const float* xp = X + (size_t)b * (CH * NPOS) + n;
#pragma unroll 8
    for (int c = 0; c < CH; c++) {
        float xv = __ldcs(xp + (size_t)c * NPOS);
        float4 w0 = *(const float4*)&wpack[c][0];
        float4 w1 = *(const float4*)&wpack[c][4];
        acc0 += xv * w0.x; acc1 += xv * w0.y;
        acc2 += xv * w0.z; acc3 += xv * w0.w;
        acc4 += xv * w1.x; acc5 += xv * w1.y;
    }

    int bn = b * NPOS + n;
    __stcs((float2*)&out[CLS_OFF + (size_t)bn * 2], make_float2(acc0, acc1));
    __stcs((float4*)&out[BBX_OFF + (size_t)bn * 4],
           make_float4(acc2, acc3, acc4, acc5));
}

// ---------------------------------------------------------------------------
// Kernel B (fused): top-100 per batch, exact jax.lax.top_k order.
// grid (NCHUNK, BATCH), 512 threads. Each block bitonic-sorts its 1000-element
// chunk (pad 1024) descending on packed u64 keys and emits its top-100.
// The LAST block per batch (atomic counter) then merges that batch's 1000
// candidates (pad 1024, second bitonic) and writes the sorted top-100 indices.
// key = ord_float(l1-l0)<<32 | (0xFFFFFFFF-n): unique; descending sort
// reproduces jax order (desc score, ties -> lower index).
// ---------------------------------------------------------------------------
__device__ __forceinline__ unsigned int ord_float(float f) {
    unsigned int b = __float_as_uint(f);
    return (b & 0x80000000u) ? ~b : (b | 0x80000000u);
}

__device__ __forceinline__ void bitonic_desc_1024(unsigned long long* key, int tid) {
    for (int k = 2; k <= CPAD; k <<= 1) {
        for (int s = k >> 1; s > 0; s >>= 1) {
#pragma unroll
            for (int i = tid; i < CPAD; i += 512) {
                int ix = i ^ s;
                if (ix > i) {
                    unsigned long long a = key[i], c = key[ix];
                    bool desc = ((i & k) == 0);
                    if (desc ? (a < c) : (a > c)) { key[i] = c; key[ix] = a; }
                }
            }
            __syncthreads();
        }
    }
}

__global__ void __launch_bounds__(512) k_topk(const float* __restrict__ cls) {
    __shared__ unsigned long long key[CPAD];   // 8 KB
    __shared__ int s_last;
    int tid = threadIdx.x;
    int j = blockIdx.x, b = blockIdx.y;

    const float2* sp = (const float2*)(cls + (size_t)b * NPOS * 2);
#pragma unroll
    for (int i = tid; i < CPAD; i += 512) {
        int n = j * CHUNKN + i;
        unsigned long long k = 0;
        if (i < CHUNKN) {
            float2 l = sp[n];
            k = ((unsigned long long)ord_float(l.y - l.x) << 32) |
                (unsigned long long)(0xFFFFFFFFu - (unsigned int)n);
        }
        key[i] = k;
    }
    __syncthreads();

    bitonic_desc_1024(key, tid);

    if (tid < KDET)
        g_cand[b * CANDN + j * KDET + tid] = key[tid];
    __threadfence();
    __syncthreads();

    if (tid == 0)
        s_last = (atomicAdd(&g_done[b], 1u) == NCHUNK - 1) ? 1 : 0;
    __syncthreads();
    if (!s_last) return;
    __threadfence();   // acquire: see all chunks' g_cand writes

    // merge: sort this batch's 1000 candidates (pad 1024), emit top-100
#pragma unroll
    for (int i = tid; i < CPAD; i += 512)
        key[i] = (i < CANDN) ? g_cand[b * CANDN + i] : 0ull;
    __syncthreads();

    bitonic_desc_1024(key, tid);

    if (tid < KDET)
        g_idx[b * KDET + tid] =
            (int)(0xFFFFFFFFu - (unsigned int)(key[tid] & 0xFFFFFFFFull));
}

// ---------------------------------------------------------------------------
// Kernel C: gather selected features (x + pos) and run 3-layer MLP + query.
// Blocks 0..99 = det (16 rows each), 100..124 = rec (16 rows each).
// 512 threads: thread = (output neuron o = tid&255, row-group rg = tid>>8).
// Each thread accumulates 8 rows (4 f32x2) for one output neuron.
// Weight loop unrolled x8 with batched LDG.64 prefetch (covers L2 latency).
// buf layout: buf[c*20 + r], r = 0..15 (stride-20 padding, 16B-aligned).
// ---------------------------------------------------------------------------
#define BUF_STRIDE 20

__device__ __forceinline__ void mlp_layer(float* __restrict__ buf,
                                          const float2* __restrict__ WT,
                                          const float* __restrict__ bias,
                                          bool relu, int o, int rg) {
    float bv = bias[o];
    unsigned long long a0 = pack2(bv, bv);
    unsigned long long a1 = a0, a2 = a0, a3 = a0;

    const float2* wp = WT + o;
    const float* bufr = buf + rg * 8;

#pragma unroll 1
    for (int cc = 0; cc < CH / 2; cc += 8) {
        // batch-load 8 weight pairs (8 LDG.64 in flight -> hides L2 latency)
        float2 w[8];
#pragma unroll
        for (int u = 0; u < 8; u++) w[u] = wp[(cc + u) * CH];

#pragma unroll
        for (int u = 0; u < 8; u++) {
            int c2 = cc + u;
            unsigned long long w0 = pack2(w[u].x, w[u].x);
            unsigned long long w1 = pack2(w[u].y, w[u].y);
            const float* base0 = bufr + (2 * c2) * BUF_STRIDE;
            const float* base1 = base0 + BUF_STRIDE;
            ulonglong2 u0 = *(const ulonglong2*)(base0);
            ulonglong2 u1 = *(const ulonglong2*)(base0 + 4);
            ulonglong2 v0 = *(const ulonglong2*)(base1);
            ulonglong2 v1 = *(const ulonglong2*)(base1 + 4);
            a0 = ffma2(u0.x, w0, a0);  a1 = ffma2(u0.y, w0, a1);
            a2 = ffma2(u1.x, w0, a2);  a3 = ffma2(u1.y, w0, a3);
            a0 = ffma2(v0.x, w1, a0);  a1 = ffma2(v0.y, w1, a1);
            a2 = ffma2(v1.x, w1, a2);  a3 = ffma2(v1.y, w1, a3);
        }
    }
    __syncthreads();   // everyone done reading buf
    {
        float2 r0 = unpack2(a0), r1 = unpack2(a1);
        float2 r2 = unpack2(a2), r3 = unpack2(a3);
        if (relu) {
            r0.x = fmaxf(r0.x, 0.f); r0.y = fmaxf(r0.y, 0.f);
            r1.x = fmaxf(r1.x, 0.f); r1.y = fmaxf(r1.y, 0.f);
            r2.x = fmaxf(r2.x, 0.f); r2.y = fmaxf(r2.y, 0.f);
            r3.x = fmaxf(r3.x, 0.f); r3.y = fmaxf(r3.y, 0.f);
        }
        float* dst = buf + o * BUF_STRIDE + rg * 8;
        *(float2*)(dst + 0) = r0;  *(float2*)(dst + 2) = r1;
        *(float2*)(dst + 4) = r2;  *(float2*)(dst + 6) = r3;
    }
    __syncthreads();   // buf ready for next layer
}

__global__ void __launch_bounds__(512) k_mlp(
        const float* __restrict__ X, const float* __restrict__ pe,
        const float* __restrict__ db1, const float* __restrict__ db2,
        const float* __restrict__ db3,
        const float* __restrict__ rb1, const float* __restrict__ rb2,
        const float* __restrict__ rb3,
        const float* __restrict__ det_q, const float* __restrict__ rec_q,
        float* __restrict__ out) {
    __shared__ float buf[CH * BUF_STRIDE];   // 20 KB
    __shared__ int   s_n[16], s_b[16], s_q[16];
    __shared__ int   s_i00[16], s_i01[16], s_i10[16], s_i11[16];
    __shared__ float s_w00[16], s_w01[16], s_w10[16], s_w11[16];

    int tid = threadIdx.x;
    int o   = tid & 255;
    int rg  = tid >> 8;
    int blk = blockIdx.x;
    bool isdet = (blk < 100);
    int rowbase = isdet ? blk * 16 : (blk - 100) * 16;

    if (tid < 16) {
        int row = rowbase + tid;
        int b, q;
        if (isdet) { b = row / KDET; q = row % KDET; }
        else       { b = row / KREC; q = row % KREC; }
        s_b[tid] = b;
        s_q[tid] = q;
        int n = g_idx[b * KDET + q];
        s_n[tid] = n;
        int i00, i01, i10, i11;
        float w00, w01, w10, w11;
        bilin_coef(n / HPIX, n % HPIX, i00, i01, i10, i11, w00, w01, w10, w11);
        s_i00[tid] = i00; s_i01[tid] = i01; s_i10[tid] = i10; s_i11[tid] = i11;
        s_w00[tid] = w00; s_w01[tid] = w01; s_w10[tid] = w10; s_w11[tid] = w11;
    }
    __syncthreads();

    // gather: buf[c*20 + r] = x[b,c,n] + pos(c,n)   (pos inlined from pe)
    // thread (o=c, rg) loads rows rg*8 .. rg*8+7
    {
        int c = o;
        const float* P = pe + c * (PHW * PHW);
#pragma unroll
        for (int r = rg * 8; r < rg * 8 + 8; r++) {
            float pv = P[s_i00[r]] * s_w00[r] + P[s_i01[r]] * s_w01[r] +
                       P[s_i10[r]] * s_w10[r] + P[s_i11[r]] * s_w11[r];
            buf[c * BUF_STRIDE + r] =
                X[((size_t)s_b[r] * CH + c) * NPOS + s_n[r]] + pv;
        }
    }
    __syncthreads();

    const float *B1, *B2, *B3, *Q;
    const float2* WT = g_WT2 + (isdet ? 0 : 3) * ((CH / 2) * CH);
    if (isdet) { B1 = db1; B2 = db2; B3 = db3; Q = det_q; }
    else       { B1 = rb1; B2 = rb2; B3 = rb3; Q = rec_q; }

    mlp_layer(buf, WT,                     B1, true,  o, rg);
    mlp_layer(buf, WT + (CH / 2) * CH,     B2, true,  o, rg);
    mlp_layer(buf, WT + 2 * (CH / 2) * CH, B3, false, o, rg);

    // epilogue: add query embedding, write output (thread covers its 8 rows)
    {
        int c = o;
#pragma unroll
        for (int r = rg * 8; r < rg * 8 + 8; r++) {
            int row = rowbase + r;
            float v = buf[c * BUF_STRIDE + r] + Q[s_q[r] * CH + c];
            size_t dst = isdet ? (DET_OFF + (size_t)row * CH + c)
                               : (REC_OFF + (size_t)row * CH + c);
            out[dst] = v;
        }
    }
}

// ---------------------------------------------------------------------------
// launch  (4 kernels; no static initializers, no attribute calls, no
// allocation APIs, no __device__ symbols passed as kernel arguments)
// ---------------------------------------------------------------------------
extern "C" void kernel_launch(void* const* d_in, const int* in_sizes, int n_in,
                              void* d_out, int out_size) {
    const float* X    = (const float*)d_in[0];
    const float* Wc   = (const float*)d_in[1];
    const float* bc   = (const float*)d_in[2];
    const float* Wb   = (const float*)d_in[3];
    const float* bb   = (const float*)d_in[4];
    const float* dW1  = (const float*)d_in[5];
    const float* db1  = (const float*)d_in[6];
    const float* dW2  = (const float*)d_in[7];
    const float* db2  = (const float*)d_in[8];
    const float* dW3  = (const float*)d_in[9];
    const float* db3  = (const float*)d_in[10];
    const float* rW1  = (const float*)d_in[11];
    const float* rb1  = (const float*)d_in[12];
    const float* rW2  = (const float*)d_in[13];
    const float* rb2  = (const float*)d_in[14];
    const float* rW3  = (const float*)d_in[15];
    const float* rb3  = (const float*)d_in[16];
    const float* detq = (const float*)d_in[17];
    const float* recq = (const float*)d_in[18];
    const float* pe   = (const float*)d_in[19];
    float* out = (float*)d_out;

    // PRE: weight transpose + posdot + counter reset (fused)
    k_pre<<<PRE_BLOCKS, 256>>>(pe, Wc, bc, Wb, bb,
                               dW1, dW2, dW3, rW1, rW2, rW3);
    // A: heads (HBM-bound main pass; writes cls+bbox into out)
    {
        dim3 grid((NPOS + 255) / 256, BATCH);
        k_heads<<<grid, 256>>>(X, Wc, Wb, out);
    }
    // B: fused top-100 (local sorts + last-block merge per batch)
    {
        dim3 grid1(NCHUNK, BATCH);
        k_topk<<<grid1, 512>>>(out + CLS_OFF);
    }
    // C: gather + MLPs + queries (512 thr: o = tid&255, row-group = tid>>8)
    k_mlp<<<125, 512>>>(X, pe, db1, db2, db3, rb1, rb2, rb3, detq, recq, out);
}

// round 16
// speedup vs baseline: 1.9064x; 1.0175x over previous
#include <cuda_runtime.h>
#include <cuda_bf16.h>

// ---------------------------------------------------------------------------
// QueryInitialization: pos-resize + det/cls heads + top-k + query MLPs
// B=16, C=256, H=W=100 (N=10000), pos 50x50, det_k=100, rec_k=25
// Outputs concatenated: det[16,100,256] | rec[16,25,256] |
//                       cls[16,10000,2] | bbox[16,10000,4]
// ---------------------------------------------------------------------------

#define BATCH 16
#define CH    256
#define NPOS  10000
#define HPIX  100
#define PHW   50
#define KDET  100
#define KREC  25

#define DET_OFF  0
#define REC_OFF  (BATCH*KDET*CH)                 // 409600
#define CLS_OFF  (REC_OFF + BATCH*KREC*CH)       // 512000
#define BBX_OFF  (CLS_OFF + BATCH*NPOS*2)        // 832000

// top-k chunking: 10 chunks x 1000 elements (padded to 1024 for bitonic)
#define NCHUNK  10
#define CHUNKN  1000
#define CPAD    1024
#define CANDN   (NCHUNK * KDET)   // 1000 candidates per batch

// k_pre grid split: wtrans blocks then posdot blocks
#define WT_BLOCKS  (8 * 8 * 6)            // 384
#define PD_BLOCKS  ((NPOS + 255) / 256)   // 40
#define PRE_BLOCKS (WT_BLOCKS + PD_BLOCKS)

// scratch (__device__ globals, accessed ONLY from device code — never passed
// as host-side kernel arguments: that hands the kernel the host shadow
// address, which ATS on the Grace host silently services -> UVM pool growth
// -> harness memory violation. Root cause of rounds 1-8.)
__device__ float  g_posdot[NPOS * 6];                // pos@[Wc;Wb]^T + bias
__device__ int    g_idx[BATCH * KDET];               // sorted top-100 / batch
__device__ float2 g_WT2[6 * (CH / 2) * CH];          // packed MLP weights
__device__ unsigned long long g_cand[BATCH * CANDN]; // chunk top-100 keys
__device__ unsigned int g_done[BATCH];               // topk arrival counters

// ---------------------------------------------------------------------------
// f32x2 packed helpers (Blackwell FFMA2)
// ---------------------------------------------------------------------------
__device__ __forceinline__ unsigned long long pack2(float x, float y) {
    unsigned long long r;
    asm("mov.b64 %0, {%1,%2};" : "=l"(r) : "f"(x), "f"(y));
    return r;
}
__device__ __forceinline__ float2 unpack2(unsigned long long v) {
    float2 f;
    asm("mov.b64 {%0,%1}, %2;" : "=f"(f.x), "=f"(f.y) : "l"(v));
    return f;
}
__device__ __forceinline__ unsigned long long ffma2(
    unsigned long long a, unsigned long long b, unsigned long long c) {
    unsigned long long d;
    asm("fma.rn.f32x2 %0, %1, %2, %3;" : "=l"(d) : "l"(a), "l"(b), "l"(c));
    return d;
}

// ---------------------------------------------------------------------------
// bilinear coefficients for output pixel (y,x) of the 50->100 upsample
// (align_corners=False; matches torch/jax reference)
// ---------------------------------------------------------------------------
__device__ __forceinline__ void bilin_coef(int y, int x,
                                           int& i00, int& i01, int& i10, int& i11,
                                           float& w00, float& w01,
                                           float& w10, float& w11) {
    float sy = 0.5f * (float)y - 0.25f;
    sy = fminf(fmaxf(sy, 0.0f), (float)(PHW - 1));
    int   y0 = (int)floorf(sy);
    float ty = sy - (float)y0;
    int   y1 = min(y0 + 1, PHW - 1);

    float sx = 0.5f * (float)x - 0.25f;
    sx = fminf(fmaxf(sx, 0.0f), (float)(PHW - 1));
    int   x0 = (int)floorf(sx);
    float tx = sx - (float)x0;
    int   x1 = min(x0 + 1, PHW - 1);

    i00 = y0 * PHW + x0;  i01 = y0 * PHW + x1;
    i10 = y1 * PHW + x0;  i11 = y1 * PHW + x1;
    w00 = (1.0f - ty) * (1.0f - tx);
    w01 = (1.0f - ty) * tx;
    w10 = ty * (1.0f - tx);
    w11 = ty * tx;
}

// ---------------------------------------------------------------------------
// Kernel PRE (fused): weight transpose + posdot precompute + counter reset.
// ---------------------------------------------------------------------------
__global__ void __launch_bounds__(256) k_pre(
        const float* __restrict__ pe,
        const float* __restrict__ Wc, const float* __restrict__ bc,
        const float* __restrict__ Wb, const float* __restrict__ bb,
        const float* __restrict__ dW1, const float* __restrict__ dW2,
        const float* __restrict__ dW3, const float* __restrict__ rW1,
        const float* __restrict__ rW2, const float* __restrict__ rW3) {
    __shared__ float tile[32][33];
    __shared__ float wpack[CH][8];

    int blk = blockIdx.x;
    int tid = threadIdx.x;

    if (blk == 0 && tid < BATCH) g_done[tid] = 0;

    if (blk < WT_BLOCKS) {
        // ---- weight transpose ----
        int l   = blk / 64;
        int rem = blk % 64;
        int oo  = (rem / 8) * 32;    // output-row tile base
        int co  = (rem % 8) * 32;    // input-col tile base
        int tx = tid % 32, ty = tid / 32;

        const float* W;
        switch (l) {
            case 0: W = dW1; break;
            case 1: W = dW2; break;
            case 2: W = dW3; break;
            case 3: W = rW1; break;
            case 4: W = rW2; break;
            default: W = rW3; break;
        }

#pragma unroll
        for (int k = 0; k < 4; k++) {
            int row = ty + 8 * k;    // o_local
            tile[row][tx] = W[(oo + row) * CH + (co + tx)];
        }
        __syncthreads();

        float2* dst = g_WT2 + l * ((CH / 2) * CH);
#pragma unroll
        for (int k = 0; k < 2; k++) {
            int c2l = ty + 8 * k;    // pair index within tile (0..15)
            float2 v = make_float2(tile[tx][2 * c2l], tile[tx][2 * c2l + 1]);
            dst[(co / 2 + c2l) * CH + (oo + tx)] = v;
        }
        return;
    }

    // ---- posdot ----
    if (tid < CH) {
        wpack[tid][0] = Wc[tid];
        wpack[tid][1] = Wc[CH + tid];
        wpack[tid][2] = Wb[tid];
        wpack[tid][3] = Wb[CH + tid];
        wpack[tid][4] = Wb[2 * CH + tid];
        wpack[tid][5] = Wb[3 * CH + tid];
        wpack[tid][6] = 0.f;
        wpack[tid][7] = 0.f;
    }
    __syncthreads();

    int n = (blk - WT_BLOCKS) * 256 + tid;
    if (n >= NPOS) return;

    int i00, i01, i10, i11;
    float w00, w01, w10, w11;
    bilin_coef(n / HPIX, n % HPIX, i00, i01, i10, i11, w00, w01, w10, w11);

    float acc0 = bc[0], acc1 = bc[1];
    float acc2 = bb[0], acc3 = bb[1], acc4 = bb[2], acc5 = bb[3];

#pragma unroll 8
    for (int c = 0; c < CH; c++) {
        const float* P = pe + c * (PHW * PHW);
        float p = P[i00] * w00 + P[i01] * w01 + P[i10] * w10 + P[i11] * w11;
        float4 w0 = *(const float4*)&wpack[c][0];
        float4 w1 = *(const float4*)&wpack[c][4];
        acc0 += p * w0.x; acc1 += p * w0.y;
        acc2 += p * w0.z; acc3 += p * w0.w;
        acc4 += p * w1.x; acc5 += p * w1.y;
    }
    float* dst = g_posdot + n * 6;
    dst[0] = acc0; dst[1] = acc1; dst[2] = acc2;
    dst[3] = acc3; dst[4] = acc4; dst[5] = acc5;
}

// ---------------------------------------------------------------------------
// Kernel A: main pass. Reads x once (163 MB, HBM-bound) with streaming
// (__ldcs, evict-first: zero reuse) and streams cls/bbox out (__stcs).
// ---------------------------------------------------------------------------
__global__ void __launch_bounds__(256) k_heads(
        const float* __restrict__ X, const float* __restrict__ Wc,
        const float* __restrict__ Wb, float* __restrict__ out) {
    __shared__ float wpack[CH][8];
    int tid = threadIdx.x;
    if (tid < CH) {
        wpack[tid][0] = Wc[tid];
        wpack[tid][1] = Wc[CH + tid];
        wpack[tid][2] = Wb[tid];
        wpack[tid][3] = Wb[CH + tid];
        wpack[tid][4] = Wb[2 * CH + tid];
        wpack[tid][5] = Wb[3 * CH + tid];
        wpack[tid][6] = 0.f;
        wpack[tid][7] = 0.f;
    }
    __syncthreads();

    int b = blockIdx.y;
    int n = blockIdx.x * blockDim.x + tid;
    if (n >= NPOS) return;

    const float* pd = g_posdot + n * 6;
    float acc0 = pd[0], acc1 = pd[1], acc2 = pd[2];
    float acc3 = pd[3], acc4 = pd[4], acc5 = pd[5];

    const float* xp = X + (size_t)b * (CH * NPOS) + n;
#pragma unroll 8
    for (int c = 0; c < CH; c++) {
        float xv = __ldcs(xp + (size_t)c * NPOS);
        float4 w0 = *(const float4*)&wpack[c][0];
        float4 w1 = *(const float4*)&wpack[c][4];
        acc0 += xv * w0.x; acc1 += xv * w0.y;
        acc2 += xv * w0.z; acc3 += xv * w0.w;
        acc4 += xv * w1.x; acc5 += xv * w1.y;
    }

    int bn = b * NPOS + n;
    __stcs((float2*)&out[CLS_OFF + (size_t)bn * 2], make_float2(acc0, acc1));
    __stcs((float4*)&out[BBX_OFF + (size_t)bn * 4],
           make_float4(acc2, acc3, acc4, acc5));
}

// ---------------------------------------------------------------------------
// Kernel B (fused): top-100 per batch, exact jax.lax.top_k order.
// g_cand is produced by one block and consumed by a DIFFERENT block, so it
// bypasses L1 (__stcg / __ldcg: L2-only — L1 is per-SM and would be wasted).
// ---------------------------------------------------------------------------
__device__ __forceinline__ unsigned int ord_float(float f) {
    unsigned int b = __float_as_uint(f);
    return (b & 0x80000000u) ? ~b : (b | 0x80000000u);
}

__device__ __forceinline__ void bitonic_desc_1024(unsigned long long* key, int tid) {
    for (int k = 2; k <= CPAD; k <<= 1) {
        for (int s = k >> 1; s > 0; s >>= 1) {
#pragma unroll
            for (int i = tid; i < CPAD; i += 512) {
                int ix = i ^ s;
                if (ix > i) {
                    unsigned long long a = key[i], c = key[ix];
                    bool desc = ((i & k) == 0);
                    if (desc ? (a < c) : (a > c)) { key[i] = c; key[ix] = a; }
                }
            }
            __syncthreads();
        }
    }
}

__global__ void __launch_bounds__(512) k_topk(const float* __restrict__ cls) {
    __shared__ unsigned long long key[CPAD];   // 8 KB
    __shared__ int s_last;
    int tid = threadIdx.x;
    int j = blockIdx.x, b = blockIdx.y;

    const float2* sp = (const float2*)(cls + (size_t)b * NPOS * 2);
#pragma unroll
    for (int i = tid; i < CPAD; i += 512) {
        int n = j * CHUNKN + i;
        unsigned long long k = 0;
        if (i < CHUNKN) {
            float2 l = sp[n];
            k = ((unsigned long long)ord_float(l.y - l.x) << 32) |
                (unsigned long long)(0xFFFFFFFFu - (unsigned int)n);
        }
        key[i] = k;
    }
    __syncthreads();

    bitonic_desc_1024(key, tid);

    if (tid < KDET)
        __stcg(&g_cand[b * CANDN + j * KDET + tid], key[tid]);
    __threadfence();
    __syncthreads();

    if (tid == 0)
        s_last = (atomicAdd(&g_done[b], 1u) == NCHUNK - 1) ? 1 : 0;
    __syncthreads();
    if (!s_last) return;
    __threadfence();   // acquire: see all chunks' g_cand writes

    // merge: sort this batch's 1000 candidates (pad 1024), emit top-100
#pragma unroll
    for (int i = tid; i < CPAD; i += 512)
        key[i] = (i < CANDN) ? __ldcg(&g_cand[b * CANDN + i]) : 0ull;
    __syncthreads();

    bitonic_desc_1024(key, tid);

    if (tid < KDET)
        g_idx[b * KDET + tid] =
            (int)(0xFFFFFFFFu - (unsigned int)(key[tid] & 0xFFFFFFFFull));
}

// ---------------------------------------------------------------------------
// Kernel C: gather selected features (x + pos) and run 3-layer MLP + query.
// Blocks 0..99 = det (16 rows each), 100..124 = rec (16 rows each).
// 1024 threads: thread = (output neuron o = tid&255, row-group rg = tid>>8,
// rg in 0..3, each handling 4 rows = 2 f32x2 accumulators).
// Weight loop: register DOUBLE-BUFFERED x8 LDG.64 prefetch — next tile's
// loads issue before current tile is consumed, hiding L2 latency (~240cyc).
// buf layout: buf[c*20 + r], r = 0..15 (stride-20 padding, 16B-aligned).
// ---------------------------------------------------------------------------
#define BUF_STRIDE 20

__device__ __forceinline__ void mlp_layer(float* __restrict__ buf,
                                          const float2* __restrict__ WT,
                                          const float* __restrict__ bias,
                                          bool relu, int o, int rg) {
    float bv = bias[o];
    unsigned long long a0 = pack2(bv, bv);
    unsigned long long a1 = a0;

    const float2* wp = WT + o;
    const float* bufr = buf + rg * 4;

    float2 w[8];
#pragma unroll
    for (int u = 0; u < 8; u++) w[u] = wp[u * CH];

#pragma unroll 1
    for (int cc = 0; cc < CH / 2; cc += 8) {
        float2 wn[8];
        if (cc + 8 < CH / 2) {
#pragma unroll
            for (int u = 0; u < 8; u++) wn[u] = wp[(cc + 8 + u) * CH];
        }
#pragma unroll
        for (int u = 0; u < 8; u++) {
            int c2 = cc + u;
            unsigned long long w0 = pack2(w[u].x, w[u].x);
            unsigned long long w1 = pack2(w[u].y, w[u].y);
            const float* base0 = bufr + (2 * c2) * BUF_STRIDE;
            ulonglong2 u0 = *(const ulonglong2*)(base0);
            ulonglong2 v0 = *(const ulonglong2*)(base0 + BUF_STRIDE);
            a0 = ffma2(u0.x, w0, a0);  a1 = ffma2(u0.y, w0, a1);
            a0 = ffma2(v0.x, w1, a0);  a1 = ffma2(v0.y, w1, a1);
        }
#pragma unroll
        for (int u = 0; u < 8; u++) w[u] = wn[u];
    }
    __syncthreads();   // everyone done reading buf
    {
        float2 r0 = unpack2(a0), r1 = unpack2(a1);
        if (relu) {
            r0.x = fmaxf(r0.x, 0.f); r0.y = fmaxf(r0.y, 0.f);
            r1.x = fmaxf(r1.x, 0.f); r1.y = fmaxf(r1.y, 0.f);
        }
        float* dst = buf + o * BUF_STRIDE + rg * 4;
        *(float2*)(dst + 0) = r0;  *(float2*)(dst + 2) = r1;
    }
    __syncthreads();   // buf ready for next layer
}

__global__ void __launch_bounds__(1024) k_mlp(
        const float* __restrict__ X, const float* __restrict__ pe,
        const float* __restrict__ db1, const float* __restrict__ db2,
        const float* __restrict__ db3,
        const float* __restrict__ rb1, const float* __restrict__ rb2,
        const float* __restrict__ rb3,
        const float* __restrict__ det_q, const float* __restrict__ rec_q,
        float* __restrict__ out) {
    __shared__ float buf[CH * BUF_STRIDE];   // 20 KB
    __shared__ int   s_n[16], s_b[16], s_q[16];
    __shared__ int   s_i00[16], s_i01[16], s_i10[16], s_i11[16];
    __shared__ float s_w00[16], s_w01[16], s_w10[16], s_w11[16];

    int tid = threadIdx.x;
    int o   = tid & 255;
    int rg  = tid >> 8;          // 0..3
    int blk = blockIdx.x;
    bool isdet = (blk < 100);
    int rowbase = isdet ? blk * 16 : (blk - 100) * 16;

    if (tid < 16) {
        int row = rowbase + tid;
        int b, q;
        if (isdet) { b = row / KDET; q = row % KDET; }
        else       { b = row / KREC; q = row % KREC; }
        s_b[tid] = b;
        s_q[tid] = q;
        int n = g_idx[b * KDET + q];
        s_n[tid] = n;
        int i00, i01, i10, i11;
        float w00, w01, w10, w11;
        bilin_coef(n / HPIX, n % HPIX, i00, i01, i10, i11, w00, w01, w10, w11);
        s_i00[tid] = i00; s_i01[tid] = i01; s_i10[tid] = i10; s_i11[tid] = i11;
        s_w00[tid] = w00; s_w01[tid] = w01; s_w10[tid] = w10; s_w11[tid] = w11;
    }
    __syncthreads();

    // gather: buf[c*20 + r] = x[b,c,n] + pos(c,n)   (pos inlined from pe)
    // thread (o=c, rg) loads rows rg*4 .. rg*4+3
    {
        int c = o;
        const float* P = pe + c * (PHW * PHW);
#pragma unroll
        for (int r = rg * 4; r < rg * 4 + 4; r++) {
            float pv = P[s_i00[r]] * s_w00[r] + P[s_i01[r]] * s_w01[r] +
                       P[s_i10[r]] * s_w10[r] + P[s_i11[r]] * s_w11[r];
            buf[c * BUF_STRIDE + r] =
                X[((size_t)s_b[r] * CH + c) * NPOS + s_n[r]] + pv;
        }
    }
    __syncthreads();

    const float *B1, *B2, *B3, *Q;
    const float2* WT = g_WT2 + (isdet ? 0 : 3) * ((CH / 2) * CH);
    if (isdet) { B1 = db1; B2 = db2; B3 = db3; Q = det_q; }
    else       { B1 = rb1; B2 = rb2; B3 = rb3; Q = rec_q; }

    mlp_layer(buf, WT,                     B1, true,  o, rg);
    mlp_layer(buf, WT + (CH / 2) * CH,     B2, true,  o, rg);
    mlp_layer(buf, WT + 2 * (CH / 2) * CH, B3, false, o, rg);

    // epilogue: add query embedding, write output (thread covers its 4 rows)
    {
        int c = o;
#pragma unroll
        for (int r = rg * 4; r < rg * 4 + 4; r++) {
            int row = rowbase + r;
            float v = buf[c * BUF_STRIDE + r] + Q[s_q[r] * CH + c];
            size_t dst = isdet ? (DET_OFF + (size_t)row * CH + c)
                               : (REC_OFF + (size_t)row * CH + c);
            out[dst] = v;
        }
    }
}

// ---------------------------------------------------------------------------
// launch  (4 kernels; no static initializers, no attribute calls, no
// allocation APIs, no __device__ symbols passed as kernel arguments)
// ---------------------------------------------------------------------------
extern "C" void kernel_launch(void* const* d_in, const int* in_sizes, int n_in,
                              void* d_out, int out_size) {
    const float* X    = (const float*)d_in[0];
    const float* Wc   = (const float*)d_in[1];
    const float* bc   = (const float*)d_in[2];
    const float* Wb   = (const float*)d_in[3];
    const float* bb   = (const float*)d_in[4];
    const float* dW1  = (const float*)d_in[5];
    const float* db1  = (const float*)d_in[6];
    const float* dW2  = (const float*)d_in[7];
    const float* db2  = (const float*)d_in[8];
    const float* dW3  = (const float*)d_in[9];
    const float* db3  = (const float*)d_in[10];
    const float* rW1  = (const float*)d_in[11];
    const float* rb1  = (const float*)d_in[12];
    const float* rW2  = (const float*)d_in[13];
    const float* rb2  = (const float*)d_in[14];
    const float* rW3  = (const float*)d_in[15];
    const float* rb3  = (const float*)d_in[16];
    const float* detq = (const float*)d_in[17];
    const float* recq = (const float*)d_in[18];
    const float* pe   = (const float*)d_in[19];
    float* out = (float*)d_out;

    // PRE: weight transpose + posdot + counter reset (fused)
    k_pre<<<PRE_BLOCKS, 256>>>(pe, Wc, bc, Wb, bb,
                               dW1, dW2, dW3, rW1, rW2, rW3);
    // A: heads (HBM-bound main pass; writes cls+bbox into out)
    {
        dim3 grid((NPOS + 255) / 256, BATCH);
        k_heads<<<grid, 256>>>(X, Wc, Wb, out);
    }
    // B: fused top-100 (local sorts + last-block merge per batch)
    {
        dim3 grid1(NCHUNK, BATCH);
        k_topk<<<grid1, 512>>>(out + CLS_OFF);
    }
    // C: gather + MLPs + queries (1024 thr: o = tid&255, rg = tid>>8)
    k_mlp<<<125, 1024>>>(X, pe, db1, db2, db3, rb1, rb2, rb3, detq, recq, out);
}